// round 1
// baseline (speedup 1.0000x reference)
#include <cuda_runtime.h>
#include <math.h>

// Problem constants
#define Bn 8
#define Sn 2048
#define En 512
#define BSn (Bn * Sn)  // 16384

__device__ __constant__ float c_inv_scale = 0.044194173824159216f; // 1/sqrt(512)

// Scratch (static device arrays — no runtime allocation allowed)
__device__ float g_q[(size_t)BSn * En];          // 32 MB
__device__ float g_k[(size_t)BSn * En];          // 32 MB
__device__ float g_v[(size_t)BSn * En];          // 32 MB
__device__ float g_delta[(size_t)Bn * Sn * Sn];  // 134 MB
__device__ float g_rowsum[BSn];

// ---------------------------------------------------------------------------
// Kernel 1: gather key/value embeddings.  grid = BSn blocks, 128 threads.
// Each block copies one row of E=512 floats (float4 vectorized) for both K & V.
// ---------------------------------------------------------------------------
__global__ __launch_bounds__(128) void gather_kv(
    const int* __restrict__ kseq, const int* __restrict__ vseq,
    const float* __restrict__ kemb, const float* __restrict__ vemb) {
    const int row = blockIdx.x;
    const int t = threadIdx.x;  // 0..127, covers 512 floats as float4
    const int ki = kseq[row];
    const int vi = vseq[row];
    const float4 kv = reinterpret_cast<const float4*>(kemb + (size_t)ki * En)[t];
    reinterpret_cast<float4*>(g_k + (size_t)row * En)[t] = kv;
    const float4 vv = reinterpret_cast<const float4*>(vemb + (size_t)vi * En)[t];
    reinterpret_cast<float4*>(g_v + (size_t)row * En)[t] = vv;
}

// ---------------------------------------------------------------------------
// Kernel 2: Q = hidden @ weight.   [16384,512] x [512,512]
// 64x64 tile, BK=16, 256 threads, 4x4 microtile per thread.
// grid = (N/64=8, M/64=256)
// ---------------------------------------------------------------------------
__global__ __launch_bounds__(256) void qgemm(
    const float* __restrict__ A, const float* __restrict__ W) {
    __shared__ float As[16][64];
    __shared__ float Bs[16][64];
    const int tid = threadIdx.x;
    const int tx = tid & 15;
    const int ty = tid >> 4;
    const int row0 = blockIdx.y * 64;
    const int col0 = blockIdx.x * 64;

    // A-load mapping: 64 rows x 16 k -> thread handles (row, 4 consecutive k)
    const int la_r = tid >> 2;
    const int la_k = (tid & 3) * 4;
    // B-load mapping: 16 k-rows x 64 cols -> thread handles (krow, 4 consecutive n)
    const int lb_k = tid >> 4;
    const int lb_c = (tid & 15) * 4;

    float acc[4][4] = {};
    for (int k0 = 0; k0 < En; k0 += 16) {
        const float4 a = *reinterpret_cast<const float4*>(
            A + (size_t)(row0 + la_r) * En + k0 + la_k);
        As[la_k + 0][la_r] = a.x;
        As[la_k + 1][la_r] = a.y;
        As[la_k + 2][la_r] = a.z;
        As[la_k + 3][la_r] = a.w;
        *reinterpret_cast<float4*>(&Bs[lb_k][lb_c]) =
            *reinterpret_cast<const float4*>(W + (size_t)(k0 + lb_k) * En + col0 + lb_c);
        __syncthreads();
#pragma unroll
        for (int kk = 0; kk < 16; kk++) {
            const float4 av = *reinterpret_cast<const float4*>(&As[kk][ty * 4]);
            const float4 bv = *reinterpret_cast<const float4*>(&Bs[kk][tx * 4]);
            const float ar[4] = {av.x, av.y, av.z, av.w};
            const float br[4] = {bv.x, bv.y, bv.z, bv.w};
#pragma unroll
            for (int i = 0; i < 4; i++)
#pragma unroll
                for (int j = 0; j < 4; j++) acc[i][j] += ar[i] * br[j];
        }
        __syncthreads();
    }
#pragma unroll
    for (int i = 0; i < 4; i++) {
        const int r = row0 + ty * 4 + i;
        *reinterpret_cast<float4*>(g_q + (size_t)r * En + col0 + tx * 4) =
            make_float4(acc[i][0], acc[i][1], acc[i][2], acc[i][3]);
    }
}

// ---------------------------------------------------------------------------
// Kernel 3: scores.  For batch b, s-tile of 64 rows: loop over all t-tiles,
// u = Q Kt^T / sqrt(E); delta = exp(u) * clip(mask,0,1); store delta;
// accumulate exact per-row sums (register partials -> shared atomics once).
// grid = (Sn/64=32, Bn=8), 256 threads.
// ---------------------------------------------------------------------------
__global__ __launch_bounds__(256) void scores(const float* __restrict__ mask) {
    const int b = blockIdx.y;
    const int s0 = blockIdx.x * 64;
    const float* Q = g_q + (size_t)b * Sn * En;
    const float* K = g_k + (size_t)b * Sn * En;
    const float* M = mask + (size_t)b * Sn * Sn;
    float* D = g_delta + (size_t)b * Sn * Sn;

    __shared__ float Qs[16][64];
    __shared__ float Ks[16][64];
    __shared__ float rsum[64];

    const int tid = threadIdx.x;
    const int tx = tid & 15;
    const int ty = tid >> 4;
    if (tid < 64) rsum[tid] = 0.0f;

    const int la_r = tid >> 2;
    const int la_k = (tid & 3) * 4;

    float rpart[4] = {0.f, 0.f, 0.f, 0.f};

    for (int t0 = 0; t0 < Sn; t0 += 64) {
        float acc[4][4] = {};
        for (int e0 = 0; e0 < En; e0 += 16) {
            const float4 a = *reinterpret_cast<const float4*>(
                Q + (size_t)(s0 + la_r) * En + e0 + la_k);
            Qs[la_k + 0][la_r] = a.x;
            Qs[la_k + 1][la_r] = a.y;
            Qs[la_k + 2][la_r] = a.z;
            Qs[la_k + 3][la_r] = a.w;
            const float4 kv = *reinterpret_cast<const float4*>(
                K + (size_t)(t0 + la_r) * En + e0 + la_k);
            Ks[la_k + 0][la_r] = kv.x;
            Ks[la_k + 1][la_r] = kv.y;
            Ks[la_k + 2][la_r] = kv.z;
            Ks[la_k + 3][la_r] = kv.w;
            __syncthreads();
#pragma unroll
            for (int kk = 0; kk < 16; kk++) {
                const float4 av = *reinterpret_cast<const float4*>(&Qs[kk][ty * 4]);
                const float4 bv = *reinterpret_cast<const float4*>(&Ks[kk][tx * 4]);
                const float ar[4] = {av.x, av.y, av.z, av.w};
                const float br[4] = {bv.x, bv.y, bv.z, bv.w};
#pragma unroll
                for (int i = 0; i < 4; i++)
#pragma unroll
                    for (int j = 0; j < 4; j++) acc[i][j] += ar[i] * br[j];
            }
            __syncthreads();
        }
        // Epilogue: exp + mask + partial row sums + store delta tile
#pragma unroll
        for (int i = 0; i < 4; i++) {
            const int s = s0 + ty * 4 + i;
            const float4 m4 = *reinterpret_cast<const float4*>(
                M + (size_t)s * Sn + t0 + tx * 4);
            const float mm[4] = {m4.x, m4.y, m4.z, m4.w};
            float d[4];
#pragma unroll
            for (int j = 0; j < 4; j++) {
                const float u = acc[i][j] * c_inv_scale;
                const float mc = fminf(fmaxf(mm[j], 0.0f), 1.0f);
                d[j] = expf(u) * mc;
                rpart[i] += d[j];
            }
            *reinterpret_cast<float4*>(D + (size_t)s * Sn + t0 + tx * 4) =
                make_float4(d[0], d[1], d[2], d[3]);
        }
    }
#pragma unroll
    for (int i = 0; i < 4; i++) atomicAdd(&rsum[ty * 4 + i], rpart[i]);
    __syncthreads();
    if (tid < 64) g_rowsum[b * Sn + s0 + tid] = rsum[tid];
}

// ---------------------------------------------------------------------------
// Kernel 4: O = (delta @ V) / (rowsum + 1e-10).
// grid = (En/64=8, Sn/64=32, Bn=8), 256 threads, 64x64 tile, BK=16, K=2048.
// ---------------------------------------------------------------------------
__global__ __launch_bounds__(256) void outgemm(float* __restrict__ out) {
    const int b = blockIdx.z;
    const int s0 = blockIdx.y * 64;
    const int e0 = blockIdx.x * 64;
    const float* D = g_delta + (size_t)b * Sn * Sn;
    const float* V = g_v + (size_t)b * Sn * En;

    __shared__ float Ds[16][64];
    __shared__ float Vs[16][64];

    const int tid = threadIdx.x;
    const int tx = tid & 15;
    const int ty = tid >> 4;

    const int la_r = tid >> 2;
    const int la_k = (tid & 3) * 4;
    const int lb_k = tid >> 4;
    const int lb_c = (tid & 15) * 4;

    float acc[4][4] = {};
    for (int t0 = 0; t0 < Sn; t0 += 16) {
        const float4 dd = *reinterpret_cast<const float4*>(
            D + (size_t)(s0 + la_r) * Sn + t0 + la_k);
        Ds[la_k + 0][la_r] = dd.x;
        Ds[la_k + 1][la_r] = dd.y;
        Ds[la_k + 2][la_r] = dd.z;
        Ds[la_k + 3][la_r] = dd.w;
        *reinterpret_cast<float4*>(&Vs[lb_k][lb_c]) =
            *reinterpret_cast<const float4*>(V + (size_t)(t0 + lb_k) * En + e0 + lb_c);
        __syncthreads();
#pragma unroll
        for (int kk = 0; kk < 16; kk++) {
            const float4 av = *reinterpret_cast<const float4*>(&Ds[kk][ty * 4]);
            const float4 bv = *reinterpret_cast<const float4*>(&Vs[kk][tx * 4]);
            const float ar[4] = {av.x, av.y, av.z, av.w};
            const float br[4] = {bv.x, bv.y, bv.z, bv.w};
#pragma unroll
            for (int i = 0; i < 4; i++)
#pragma unroll
                for (int j = 0; j < 4; j++) acc[i][j] += ar[i] * br[j];
        }
        __syncthreads();
    }
#pragma unroll
    for (int i = 0; i < 4; i++) {
        const int s = s0 + ty * 4 + i;
        const float inv = 1.0f / (g_rowsum[b * Sn + s] + 1e-10f);
        *reinterpret_cast<float4*>(out + ((size_t)b * Sn + s) * En + e0 + tx * 4) =
            make_float4(acc[i][0] * inv, acc[i][1] * inv, acc[i][2] * inv,
                        acc[i][3] * inv);
    }
}

// ---------------------------------------------------------------------------
// Launch
// Inputs (metadata order): key_seq[i32], value_seq[i32], hidden[f32],
// mask_matrix[f32], nan_matrix[i32, unused], key_emb[f32], value_emb[f32],
// weight[f32]. Output: [B,S,E] f32.
// ---------------------------------------------------------------------------
extern "C" void kernel_launch(void* const* d_in, const int* in_sizes, int n_in,
                              void* d_out, int out_size) {
    const int* key_seq = (const int*)d_in[0];
    const int* value_seq = (const int*)d_in[1];
    const float* hidden = (const float*)d_in[2];
    const float* mask = (const float*)d_in[3];
    const float* key_emb = (const float*)d_in[5];
    const float* value_emb = (const float*)d_in[6];
    const float* weight = (const float*)d_in[7];
    float* out = (float*)d_out;

    gather_kv<<<BSn, 128>>>(key_seq, value_seq, key_emb, value_emb);
    qgemm<<<dim3(En / 64, BSn / 64), 256>>>(hidden, weight);
    scores<<<dim3(Sn / 64, Bn), 256>>>(mask);
    outgemm<<<dim3(En / 64, Sn / 64, Bn), 256>>>(out);
}

// round 2
// speedup vs baseline: 1.2190x; 1.2190x over previous
#include <cuda_runtime.h>
#include <math.h>

#define Bn 8
#define Sn 2048
#define En 512
#define BSn (Bn * Sn)  // 16384

typedef unsigned long long ULL;

__device__ __constant__ float c_inv_scale = 0.044194173824159216f; // 1/sqrt(512)

// Scratch (static device arrays — no runtime allocation allowed)
__device__ float g_q[(size_t)BSn * En];          // 32 MB
__device__ float g_k[(size_t)BSn * En];          // 32 MB
__device__ float g_v[(size_t)BSn * En];          // 32 MB
__device__ float g_delta[(size_t)Bn * Sn * Sn];  // 134 MB
__device__ float g_rowsum[BSn];

// ---- packed f32x2 helpers (FFMA2 — ptxas never emits this from C++) ----
__device__ __forceinline__ ULL pack2(float x, float y) {
    ULL r;
    asm("mov.b64 %0, {%1,%2};" : "=l"(r) : "f"(x), "f"(y));
    return r;
}
__device__ __forceinline__ ULL fma2(ULL a, ULL b, ULL c) {
    ULL d;
    asm("fma.rn.f32x2 %0, %1, %2, %3;" : "=l"(d) : "l"(a), "l"(b), "l"(c));
    return d;
}
__device__ __forceinline__ float2 unpack2(ULL v) {
    float2 f;
    asm("mov.b64 {%0,%1}, %2;" : "=f"(f.x), "=f"(f.y) : "l"(v));
    return f;
}

// ---------------------------------------------------------------------------
// Kernel 1: gather key/value embeddings.
// ---------------------------------------------------------------------------
__global__ __launch_bounds__(128) void gather_kv(
    const int* __restrict__ kseq, const int* __restrict__ vseq,
    const float* __restrict__ kemb, const float* __restrict__ vemb) {
    const int row = blockIdx.x;
    const int t = threadIdx.x;
    const int ki = kseq[row];
    const int vi = vseq[row];
    reinterpret_cast<float4*>(g_k + (size_t)row * En)[t] =
        reinterpret_cast<const float4*>(kemb + (size_t)ki * En)[t];
    reinterpret_cast<float4*>(g_v + (size_t)row * En)[t] =
        reinterpret_cast<const float4*>(vemb + (size_t)vi * En)[t];
}

// ---------------------------------------------------------------------------
// Kernel 2: Q = hidden @ weight.  [16384,512]x[512,512]
// 128x128 tile, BK=16, 256 threads, 8x8 microtile, f32x2 FMA.
// grid = (512/128=4, 16384/128=128)
// ---------------------------------------------------------------------------
__global__ __launch_bounds__(256) void qgemm(
    const float* __restrict__ A, const float* __restrict__ W) {
    __shared__ __align__(16) float As[16][128];
    __shared__ __align__(16) float Bs[16][128];
    const int tid = threadIdx.x;
    const int tx = tid & 15;
    const int ty = tid >> 4;
    const int row0 = blockIdx.y * 128;
    const int col0 = blockIdx.x * 128;

    const int la_r = tid >> 1;
    const int la_k = (tid & 1) * 8;
    const int lb_k = tid >> 4;
    const int lb_c = (tid & 15) * 8;

    const float* Aptr = A + (size_t)(row0 + la_r) * En + la_k;
    const float* Bptr = W + (size_t)lb_k * En + col0 + lb_c;

    float4 pa0 = *(const float4*)(Aptr);
    float4 pa1 = *(const float4*)(Aptr + 4);
    float4 pb0 = *(const float4*)(Bptr);
    float4 pb1 = *(const float4*)(Bptr + 4);

    ULL acc[8][4] = {};

    for (int k0 = 0; k0 < En; k0 += 16) {
        As[la_k + 0][la_r] = pa0.x;
        As[la_k + 1][la_r] = pa0.y;
        As[la_k + 2][la_r] = pa0.z;
        As[la_k + 3][la_r] = pa0.w;
        As[la_k + 4][la_r] = pa1.x;
        As[la_k + 5][la_r] = pa1.y;
        As[la_k + 6][la_r] = pa1.z;
        As[la_k + 7][la_r] = pa1.w;
        *(float4*)&Bs[lb_k][lb_c] = pb0;
        *(float4*)&Bs[lb_k][lb_c + 4] = pb1;
        __syncthreads();
        if (k0 + 16 < En) {
            pa0 = *(const float4*)(Aptr + k0 + 16);
            pa1 = *(const float4*)(Aptr + k0 + 20);
            pb0 = *(const float4*)(Bptr + (size_t)(k0 + 16) * En);
            pb1 = *(const float4*)(Bptr + (size_t)(k0 + 16) * En + 4);
        }
#pragma unroll
        for (int kk = 0; kk < 16; kk++) {
            const float4 a0 = *(const float4*)&As[kk][ty * 8];
            const float4 a1 = *(const float4*)&As[kk][ty * 8 + 4];
            const ulonglong2 b01 = *(const ulonglong2*)&Bs[kk][tx * 8];
            const ulonglong2 b23 = *(const ulonglong2*)&Bs[kk][tx * 8 + 4];
            const float av[8] = {a0.x, a0.y, a0.z, a0.w, a1.x, a1.y, a1.z, a1.w};
            const ULL bv[4] = {b01.x, b01.y, b23.x, b23.y};
#pragma unroll
            for (int i = 0; i < 8; i++) {
                const ULL ad = pack2(av[i], av[i]);
                acc[i][0] = fma2(ad, bv[0], acc[i][0]);
                acc[i][1] = fma2(ad, bv[1], acc[i][1]);
                acc[i][2] = fma2(ad, bv[2], acc[i][2]);
                acc[i][3] = fma2(ad, bv[3], acc[i][3]);
            }
        }
        __syncthreads();
    }
#pragma unroll
    for (int i = 0; i < 8; i++) {
        const float2 c0 = unpack2(acc[i][0]);
        const float2 c1 = unpack2(acc[i][1]);
        const float2 c2 = unpack2(acc[i][2]);
        const float2 c3 = unpack2(acc[i][3]);
        float* op = g_q + (size_t)(row0 + ty * 8 + i) * En + col0 + tx * 8;
        *(float4*)op = make_float4(c0.x, c0.y, c1.x, c1.y);
        *(float4*)(op + 4) = make_float4(c2.x, c2.y, c3.x, c3.y);
    }
}

// ---------------------------------------------------------------------------
// Kernel 3: scores. s-tile of 128 rows; loop over 16 t-tiles of 128.
// delta = exp(QK^T/sqrt(E)) * clip(mask); store delta, exact rowsums.
// grid = (Sn/128=16, Bn=8), 256 threads.
// ---------------------------------------------------------------------------
__global__ __launch_bounds__(256) void scores(const float* __restrict__ mask) {
    const int b = blockIdx.y;
    const int s0 = blockIdx.x * 128;
    const float* Q = g_q + (size_t)b * Sn * En;
    const float* K = g_k + (size_t)b * Sn * En;
    const float* M = mask + (size_t)b * Sn * Sn;
    float* D = g_delta + (size_t)b * Sn * Sn;

    __shared__ __align__(16) float Qs[16][128];
    __shared__ __align__(16) float Ks[16][128];
    __shared__ float rsum[128];

    const int tid = threadIdx.x;
    const int tx = tid & 15;
    const int ty = tid >> 4;
    if (tid < 128) rsum[tid] = 0.0f;

    const int l_r = tid >> 1;
    const int l_k = (tid & 1) * 8;

    const float* Qb = Q + (size_t)(s0 + l_r) * En + l_k;

    float rpart[8] = {};

    for (int t0 = 0; t0 < Sn; t0 += 128) {
        const float* Kb = K + (size_t)(t0 + l_r) * En + l_k;
        ULL acc[8][4] = {};
        float4 qa0 = *(const float4*)(Qb);
        float4 qa1 = *(const float4*)(Qb + 4);
        float4 ka0 = *(const float4*)(Kb);
        float4 ka1 = *(const float4*)(Kb + 4);
        for (int e0 = 0; e0 < En; e0 += 16) {
            Qs[l_k + 0][l_r] = qa0.x;
            Qs[l_k + 1][l_r] = qa0.y;
            Qs[l_k + 2][l_r] = qa0.z;
            Qs[l_k + 3][l_r] = qa0.w;
            Qs[l_k + 4][l_r] = qa1.x;
            Qs[l_k + 5][l_r] = qa1.y;
            Qs[l_k + 6][l_r] = qa1.z;
            Qs[l_k + 7][l_r] = qa1.w;
            Ks[l_k + 0][l_r] = ka0.x;
            Ks[l_k + 1][l_r] = ka0.y;
            Ks[l_k + 2][l_r] = ka0.z;
            Ks[l_k + 3][l_r] = ka0.w;
            Ks[l_k + 4][l_r] = ka1.x;
            Ks[l_k + 5][l_r] = ka1.y;
            Ks[l_k + 6][l_r] = ka1.z;
            Ks[l_k + 7][l_r] = ka1.w;
            __syncthreads();
            if (e0 + 16 < En) {
                qa0 = *(const float4*)(Qb + e0 + 16);
                qa1 = *(const float4*)(Qb + e0 + 20);
                ka0 = *(const float4*)(Kb + e0 + 16);
                ka1 = *(const float4*)(Kb + e0 + 20);
            }
#pragma unroll
            for (int kk = 0; kk < 16; kk++) {
                const float4 a0 = *(const float4*)&Qs[kk][ty * 8];
                const float4 a1 = *(const float4*)&Qs[kk][ty * 8 + 4];
                const ulonglong2 b01 = *(const ulonglong2*)&Ks[kk][tx * 8];
                const ulonglong2 b23 = *(const ulonglong2*)&Ks[kk][tx * 8 + 4];
                const float av[8] = {a0.x, a0.y, a0.z, a0.w, a1.x, a1.y, a1.z, a1.w};
                const ULL bv[4] = {b01.x, b01.y, b23.x, b23.y};
#pragma unroll
                for (int i = 0; i < 8; i++) {
                    const ULL ad = pack2(av[i], av[i]);
                    acc[i][0] = fma2(ad, bv[0], acc[i][0]);
                    acc[i][1] = fma2(ad, bv[1], acc[i][1]);
                    acc[i][2] = fma2(ad, bv[2], acc[i][2]);
                    acc[i][3] = fma2(ad, bv[3], acc[i][3]);
                }
            }
            __syncthreads();
        }
        // Epilogue: exp + mask + partial row sums + store delta tile
#pragma unroll
        for (int i = 0; i < 8; i++) {
            const int s = s0 + ty * 8 + i;
            const float* mp = M + (size_t)s * Sn + t0 + tx * 8;
            const float4 m0 = *(const float4*)(mp);
            const float4 m1 = *(const float4*)(mp + 4);
            const float mm[8] = {m0.x, m0.y, m0.z, m0.w, m1.x, m1.y, m1.z, m1.w};
            const float2 c0 = unpack2(acc[i][0]);
            const float2 c1 = unpack2(acc[i][1]);
            const float2 c2 = unpack2(acc[i][2]);
            const float2 c3 = unpack2(acc[i][3]);
            const float u[8] = {c0.x, c0.y, c1.x, c1.y, c2.x, c2.y, c3.x, c3.y};
            float d[8];
#pragma unroll
            for (int j = 0; j < 8; j++) {
                const float mc = fminf(fmaxf(mm[j], 0.0f), 1.0f);
                d[j] = expf(u[j] * c_inv_scale) * mc;
                rpart[i] += d[j];
            }
            float* dp = D + (size_t)s * Sn + t0 + tx * 8;
            *(float4*)dp = make_float4(d[0], d[1], d[2], d[3]);
            *(float4*)(dp + 4) = make_float4(d[4], d[5], d[6], d[7]);
        }
    }
#pragma unroll
    for (int i = 0; i < 8; i++) atomicAdd(&rsum[ty * 8 + i], rpart[i]);
    __syncthreads();
    if (tid < 128) g_rowsum[b * Sn + s0 + tid] = rsum[tid];
}

// ---------------------------------------------------------------------------
// Kernel 4: O = (delta @ V) / (rowsum + 1e-10).
// grid = (512/128=4, 2048/128=16, 8), 256 threads, 128x128 tile, BK=16.
// ---------------------------------------------------------------------------
__global__ __launch_bounds__(256) void outgemm(float* __restrict__ out) {
    const int b = blockIdx.z;
    const int s0 = blockIdx.y * 128;
    const int e0c = blockIdx.x * 128;
    const float* D = g_delta + (size_t)b * Sn * Sn;
    const float* V = g_v + (size_t)b * Sn * En;

    __shared__ __align__(16) float Ds[16][128];
    __shared__ __align__(16) float Vs[16][128];

    const int tid = threadIdx.x;
    const int tx = tid & 15;
    const int ty = tid >> 4;

    const int la_r = tid >> 1;
    const int la_k = (tid & 1) * 8;
    const int lb_k = tid >> 4;
    const int lb_c = (tid & 15) * 8;

    const float* Aptr = D + (size_t)(s0 + la_r) * Sn + la_k;
    const float* Bptr = V + (size_t)lb_k * En + e0c + lb_c;

    float4 pa0 = *(const float4*)(Aptr);
    float4 pa1 = *(const float4*)(Aptr + 4);
    float4 pb0 = *(const float4*)(Bptr);
    float4 pb1 = *(const float4*)(Bptr + 4);

    ULL acc[8][4] = {};

    for (int t0 = 0; t0 < Sn; t0 += 16) {
        Ds[la_k + 0][la_r] = pa0.x;
        Ds[la_k + 1][la_r] = pa0.y;
        Ds[la_k + 2][la_r] = pa0.z;
        Ds[la_k + 3][la_r] = pa0.w;
        Ds[la_k + 4][la_r] = pa1.x;
        Ds[la_k + 5][la_r] = pa1.y;
        Ds[la_k + 6][la_r] = pa1.z;
        Ds[la_k + 7][la_r] = pa1.w;
        *(float4*)&Vs[lb_k][lb_c] = pb0;
        *(float4*)&Vs[lb_k][lb_c + 4] = pb1;
        __syncthreads();
        if (t0 + 16 < Sn) {
            pa0 = *(const float4*)(Aptr + t0 + 16);
            pa1 = *(const float4*)(Aptr + t0 + 20);
            pb0 = *(const float4*)(Bptr + (size_t)(t0 + 16) * En);
            pb1 = *(const float4*)(Bptr + (size_t)(t0 + 16) * En + 4);
        }
#pragma unroll
        for (int kk = 0; kk < 16; kk++) {
            const float4 a0 = *(const float4*)&Ds[kk][ty * 8];
            const float4 a1 = *(const float4*)&Ds[kk][ty * 8 + 4];
            const ulonglong2 b01 = *(const ulonglong2*)&Vs[kk][tx * 8];
            const ulonglong2 b23 = *(const ulonglong2*)&Vs[kk][tx * 8 + 4];
            const float av[8] = {a0.x, a0.y, a0.z, a0.w, a1.x, a1.y, a1.z, a1.w};
            const ULL bv[4] = {b01.x, b01.y, b23.x, b23.y};
#pragma unroll
            for (int i = 0; i < 8; i++) {
                const ULL ad = pack2(av[i], av[i]);
                acc[i][0] = fma2(ad, bv[0], acc[i][0]);
                acc[i][1] = fma2(ad, bv[1], acc[i][1]);
                acc[i][2] = fma2(ad, bv[2], acc[i][2]);
                acc[i][3] = fma2(ad, bv[3], acc[i][3]);
            }
        }
        __syncthreads();
    }
#pragma unroll
    for (int i = 0; i < 8; i++) {
        const int s = s0 + ty * 8 + i;
        const float inv = 1.0f / (g_rowsum[b * Sn + s] + 1e-10f);
        const float2 c0 = unpack2(acc[i][0]);
        const float2 c1 = unpack2(acc[i][1]);
        const float2 c2 = unpack2(acc[i][2]);
        const float2 c3 = unpack2(acc[i][3]);
        float* op = out + ((size_t)b * Sn + s) * En + e0c + tx * 8;
        *(float4*)op = make_float4(c0.x * inv, c0.y * inv, c1.x * inv, c1.y * inv);
        *(float4*)(op + 4) = make_float4(c2.x * inv, c2.y * inv, c3.x * inv, c3.y * inv);
    }
}

// ---------------------------------------------------------------------------
// Launch
// ---------------------------------------------------------------------------
extern "C" void kernel_launch(void* const* d_in, const int* in_sizes, int n_in,
                              void* d_out, int out_size) {
    const int* key_seq = (const int*)d_in[0];
    const int* value_seq = (const int*)d_in[1];
    const float* hidden = (const float*)d_in[2];
    const float* mask = (const float*)d_in[3];
    const float* key_emb = (const float*)d_in[5];
    const float* value_emb = (const float*)d_in[6];
    const float* weight = (const float*)d_in[7];
    float* out = (float*)d_out;

    gather_kv<<<BSn, 128>>>(key_seq, value_seq, key_emb, value_emb);
    qgemm<<<dim3(En / 128, BSn / 128), 256>>>(hidden, weight);
    scores<<<dim3(Sn / 128, Bn), 256>>>(mask);
    outgemm<<<dim3(En / 128, Sn / 128, Bn), 256>>>(out);
}

// round 4
// speedup vs baseline: 1.4646x; 1.2015x over previous
#include <cuda_runtime.h>
#include <cuda_fp16.h>
#include <math.h>
#include <stdint.h>

#define Bn 8
#define Sn 2048
#define En 512
#define BSn (Bn * Sn)  // 16384

__device__ __constant__ float c_inv_scale = 0.044194173824159216f; // 1/sqrt(512)

// ---------------- scratch (static device arrays; no runtime alloc) --------
__device__ __half g_hhi[(size_t)BSn * En];
__device__ __half g_hlo[(size_t)BSn * En];
__device__ __half g_wThi[(size_t)En * En];   // [e_out][e_in]
__device__ __half g_wTlo[(size_t)En * En];
__device__ __half g_qhi[(size_t)BSn * En];   // pre-scaled by 1/sqrt(E)
__device__ __half g_qlo[(size_t)BSn * En];
__device__ __half g_khi[(size_t)BSn * En];
__device__ __half g_klo[(size_t)BSn * En];
__device__ __half g_vThi[(size_t)Bn * En * Sn];  // [b][e][t]
__device__ __half g_vTlo[(size_t)Bn * En * Sn];
__device__ __half g_dhi[(size_t)Bn * Sn * Sn];   // delta [b*S + s][t]
__device__ __half g_dlo[(size_t)Bn * Sn * Sn];
__device__ float g_rowsum[BSn];

// ---------------- helpers ---------------------------------------------
__device__ __forceinline__ uint32_t smem_u32(const void* p) {
    uint32_t a;
    asm("{ .reg .u64 t; cvta.to.shared.u64 t, %1; cvt.u32.u64 %0, t; }"
        : "=r"(a) : "l"(p));
    return a;
}
__device__ __forceinline__ void ldsm_x4(uint32_t (&r)[4], uint32_t addr) {
    asm volatile(
        "ldmatrix.sync.aligned.m8n8.x4.shared.b16 {%0,%1,%2,%3}, [%4];"
        : "=r"(r[0]), "=r"(r[1]), "=r"(r[2]), "=r"(r[3]) : "r"(addr));
}
__device__ __forceinline__ void mma16816(float (&d)[4], const uint32_t (&a)[4],
                                         uint32_t b0, uint32_t b1) {
    asm volatile(
        "mma.sync.aligned.m16n8k16.row.col.f32.f16.f16.f32 "
        "{%0,%1,%2,%3}, {%4,%5,%6,%7}, {%8,%9}, {%0,%1,%2,%3};"
        : "+f"(d[0]), "+f"(d[1]), "+f"(d[2]), "+f"(d[3])
        : "r"(a[0]), "r"(a[1]), "r"(a[2]), "r"(a[3]), "r"(b0), "r"(b1));
}
__device__ __forceinline__ void split_f(float x, __half& h, __half& l) {
    h = __float2half_rn(x);
    l = __float2half_rn(x - __half2float(h));
}
__device__ __forceinline__ uint32_t h2u(__half a, __half b) {
    __half2 p = __halves2half2(a, b);
    return *reinterpret_cast<uint32_t*>(&p);
}
__device__ __forceinline__ void store_split2(float x, float y, __half* hi,
                                             __half* lo) {
    __half hx, lx, hy, ly;
    split_f(x, hx, lx);
    split_f(y, hy, ly);
    *(uint32_t*)hi = h2u(hx, hy);
    *(uint32_t*)lo = h2u(lx, ly);
}

// ---------------------------------------------------------------------------
// HMMA mainloop: acc[128x128 tile] += Ahi·Bhi^T + Alo·Bhi^T + Ahi·Blo^T over
// K = ktot. A, B both K-major fp16 (row strides lda/ldb). 256 threads.
// Block tile 128x128, K-chunk 32, double-buffered smem (pad stride 40 halves).
// Warp w: wm=(w&1)*64, wn=(w>>1)*32; per warp 64x32 = acc[4][4][4] fp32.
// ---------------------------------------------------------------------------
#define PAD 40
__device__ __forceinline__ void hmma_gemm(
    const __half* __restrict__ Ahi, const __half* __restrict__ Alo,
    const __half* __restrict__ Bhi, const __half* __restrict__ Blo,
    int lda, int ldb, int ktot, float (&acc)[4][4][4]) {
    __shared__ __align__(16) __half As[2][128][PAD];
    __shared__ __align__(16) __half Bs[2][128][PAD];
    const int tid = threadIdx.x;
    const int w = tid >> 5, l = tid & 31;
    const int wm = (w & 1) * 64, wn = (w >> 1) * 32;
    const int lrow = l & 7, quad = l >> 3;

    const int grow = tid >> 1, gc = (tid & 1) * 16;
    const int nck = ktot / 32;
    const int total = nck * 3;

    uint32_t a_addr[4][2], b_addr[2][2];
    {
        const uint32_t As0 = smem_u32(&As[0][0][0]);
        const uint32_t Bs0 = smem_u32(&Bs[0][0][0]);
#pragma unroll
        for (int mi = 0; mi < 4; mi++)
#pragma unroll
            for (int ks = 0; ks < 2; ks++)
                a_addr[mi][ks] =
                    As0 + ((wm + mi * 16 + (quad & 1) * 8 + lrow) * PAD +
                           ks * 16 + (quad >> 1) * 8) * 2;
#pragma unroll
        for (int bi = 0; bi < 2; bi++)
#pragma unroll
            for (int ks = 0; ks < 2; ks++)
                b_addr[bi][ks] =
                    Bs0 + ((wn + bi * 16 + (quad >> 1) * 8 + lrow) * PAD +
                           ks * 16 + (quad & 1) * 8) * 2;
    }

    uint4 ra0, ra1, rb0, rb1;
    {
        const __half* Ap = Ahi + (size_t)grow * lda + gc;
        const __half* Bp = Bhi + (size_t)grow * ldb + gc;
        ra0 = *(const uint4*)Ap;
        ra1 = *(const uint4*)(Ap + 8);
        rb0 = *(const uint4*)Bp;
        rb1 = *(const uint4*)(Bp + 8);
    }

    for (int c = 0; c < total; c++) {
        const int buf = c & 1;
        *(uint4*)&As[buf][grow][gc] = ra0;
        *(uint4*)&As[buf][grow][gc + 8] = ra1;
        *(uint4*)&Bs[buf][grow][gc] = rb0;
        *(uint4*)&Bs[buf][grow][gc + 8] = rb1;
        __syncthreads();
        if (c + 1 < total) {
            const int cn = c + 1;
            const int pass = cn / nck;
            const int kc = (cn - pass * nck) * 32;
            const __half* Ap =
                ((pass == 1) ? Alo : Ahi) + (size_t)grow * lda + kc + gc;
            const __half* Bp =
                ((pass == 2) ? Blo : Bhi) + (size_t)grow * ldb + kc + gc;
            ra0 = *(const uint4*)Ap;
            ra1 = *(const uint4*)(Ap + 8);
            rb0 = *(const uint4*)Bp;
            rb1 = *(const uint4*)(Bp + 8);
        }
        const uint32_t boff = buf ? (uint32_t)(128 * PAD * 2) : 0u;
#pragma unroll
        for (int ks = 0; ks < 2; ks++) {
            uint32_t af[4][4], bf[2][4];
#pragma unroll
            for (int mi = 0; mi < 4; mi++) ldsm_x4(af[mi], a_addr[mi][ks] + boff);
#pragma unroll
            for (int bi = 0; bi < 2; bi++) ldsm_x4(bf[bi], b_addr[bi][ks] + boff);
#pragma unroll
            for (int mi = 0; mi < 4; mi++)
#pragma unroll
                for (int ni = 0; ni < 4; ni++)
                    mma16816(acc[mi][ni], af[mi], bf[ni >> 1][(ni & 1) * 2],
                             bf[ni >> 1][(ni & 1) * 2 + 1]);
        }
        __syncthreads();
    }
}

// ---------------------------------------------------------------------------
// Prep kernels
// ---------------------------------------------------------------------------
__global__ __launch_bounds__(256) void split_hidden(const float* __restrict__ h) {
    const size_t i8 = ((size_t)blockIdx.x * 256 + threadIdx.x) * 8;
    const float4 f0 = *(const float4*)(h + i8);
    const float4 f1 = *(const float4*)(h + i8 + 4);
    const float v[8] = {f0.x, f0.y, f0.z, f0.w, f1.x, f1.y, f1.z, f1.w};
    __half hh[8], ll[8];
#pragma unroll
    for (int j = 0; j < 8; j++) split_f(v[j], hh[j], ll[j]);
    *(uint4*)(g_hhi + i8) = make_uint4(h2u(hh[0], hh[1]), h2u(hh[2], hh[3]),
                                       h2u(hh[4], hh[5]), h2u(hh[6], hh[7]));
    *(uint4*)(g_hlo + i8) = make_uint4(h2u(ll[0], ll[1]), h2u(ll[2], ll[3]),
                                       h2u(ll[4], ll[5]), h2u(ll[6], ll[7]));
}

__global__ __launch_bounds__(256) void transpose_w(const float* __restrict__ W) {
    const int idx = blockIdx.x * 256 + threadIdx.x;  // over 512*512
    const int eo = idx >> 9;
    const int ei = idx & 511;
    const float x = W[(size_t)ei * En + eo];
    __half hh, ll;
    split_f(x, hh, ll);
    g_wThi[idx] = hh;
    g_wTlo[idx] = ll;
}

__global__ __launch_bounds__(128) void gather_k(const int* __restrict__ kseq,
                                                const float* __restrict__ kemb) {
    const int row = blockIdx.x;
    const int t = threadIdx.x;  // 0..127
    const int ki = kseq[row];
    const float4 f = *(const float4*)(kemb + (size_t)ki * En + t * 4);
    __half h0, l0, h1, l1, h2, l2, h3, l3;
    split_f(f.x, h0, l0);
    split_f(f.y, h1, l1);
    split_f(f.z, h2, l2);
    split_f(f.w, h3, l3);
    *(uint2*)(g_khi + (size_t)row * En + t * 4) = make_uint2(h2u(h0, h1), h2u(h2, h3));
    *(uint2*)(g_klo + (size_t)row * En + t * 4) = make_uint2(h2u(l0, l1), h2u(l2, l3));
}

__global__ __launch_bounds__(256) void gather_vT(const int* __restrict__ vseq,
                                                 const float* __restrict__ vemb) {
    __shared__ float tile[64][65];
    const int b = blockIdx.z;
    const int e0 = blockIdx.y * 64;
    const int t0 = blockIdx.x * 64;
    const int tid = threadIdx.x;
    const int tr = tid >> 4;
    const int tc = (tid & 15) * 4;
#pragma unroll
    for (int rr = 0; rr < 4; rr++) {
        const int tl = tr + rr * 16;
        const int vi = vseq[b * Sn + t0 + tl];
        const float4 f = *(const float4*)(vemb + (size_t)vi * En + e0 + tc);
        tile[tl][tc + 0] = f.x;
        tile[tl][tc + 1] = f.y;
        tile[tl][tc + 2] = f.z;
        tile[tl][tc + 3] = f.w;
    }
    __syncthreads();
    const int er = tid >> 3;
    const int seg = (tid & 7) * 8;
#pragma unroll
    for (int pp = 0; pp < 2; pp++) {
        const int el = er + pp * 32;
        __half hh[8], ll[8];
#pragma unroll
        for (int j = 0; j < 8; j++) split_f(tile[seg + j][el], hh[j], ll[j]);
        const size_t o = ((size_t)b * En + e0 + el) * Sn + t0 + seg;
        *(uint4*)(g_vThi + o) = make_uint4(h2u(hh[0], hh[1]), h2u(hh[2], hh[3]),
                                           h2u(hh[4], hh[5]), h2u(hh[6], hh[7]));
        *(uint4*)(g_vTlo + o) = make_uint4(h2u(ll[0], ll[1]), h2u(ll[2], ll[3]),
                                           h2u(ll[4], ll[5]), h2u(ll[6], ll[7]));
    }
}

__global__ __launch_bounds__(256) void zero_rowsum() {
    g_rowsum[blockIdx.x * 256 + threadIdx.x] = 0.0f;
}

// ---------------------------------------------------------------------------
// GEMM kernels (256 threads each)
// ---------------------------------------------------------------------------
// Q = (H @ W) * inv_scale, split to fp16.  grid = (En/128=4, BSn/128=128)
__global__ __launch_bounds__(256) void qgemm_h() {
    const int s0 = blockIdx.y * 128;
    const int n0 = blockIdx.x * 128;
    float acc[4][4][4] = {};
    hmma_gemm(g_hhi + (size_t)s0 * En, g_hlo + (size_t)s0 * En,
              g_wThi + (size_t)n0 * En, g_wTlo + (size_t)n0 * En, En, En, En,
              acc);
    const int tid = threadIdx.x;
    const int w = tid >> 5, l = tid & 31;
    const int wm = (w & 1) * 64, wn = (w >> 1) * 32;
#pragma unroll
    for (int mi = 0; mi < 4; mi++) {
#pragma unroll
        for (int rh = 0; rh < 2; rh++) {
            const int row = s0 + wm + mi * 16 + (l >> 2) + rh * 8;
#pragma unroll
            for (int ni = 0; ni < 4; ni++) {
                const int col = n0 + wn + ni * 8 + (l & 3) * 2;
                const size_t o = (size_t)row * En + col;
                store_split2(acc[mi][ni][rh * 2] * c_inv_scale,
                             acc[mi][ni][rh * 2 + 1] * c_inv_scale,
                             g_qhi + o, g_qlo + o);
            }
        }
    }
}

// delta = exp(Q K^T) * clip(mask); rowsums.  grid = (t=16, s=16, b=8)
__global__ __launch_bounds__(256) void scores_h(const float* __restrict__ mask) {
    const int b = blockIdx.z;
    const int s0 = blockIdx.y * 128;
    const int t0 = blockIdx.x * 128;
    const size_t qoff = ((size_t)b * Sn + s0) * En;
    const size_t koff = ((size_t)b * Sn + t0) * En;
    float acc[4][4][4] = {};
    hmma_gemm(g_qhi + qoff, g_qlo + qoff, g_khi + koff, g_klo + koff, En, En,
              En, acc);
    __shared__ float rsum[128];
    const int tid = threadIdx.x;
    if (tid < 128) rsum[tid] = 0.0f;
    __syncthreads();
    const int w = tid >> 5, l = tid & 31;
    const int wm = (w & 1) * 64, wn = (w >> 1) * 32;
#pragma unroll
    for (int mi = 0; mi < 4; mi++) {
#pragma unroll
        for (int rh = 0; rh < 2; rh++) {
            const int lr = wm + mi * 16 + (l >> 2) + rh * 8;
            const size_t grow = (size_t)b * Sn + s0 + lr;
            const float* mrow = mask + grow * Sn + t0;
            __half* dh = g_dhi + grow * Sn + t0;
            __half* dl = g_dlo + grow * Sn + t0;
            float part = 0.0f;
#pragma unroll
            for (int ni = 0; ni < 4; ni++) {
                const int col = wn + ni * 8 + (l & 3) * 2;
                const float2 m2 = *(const float2*)(mrow + col);
                const float mc0 = fminf(fmaxf(m2.x, 0.0f), 1.0f);
                const float mc1 = fminf(fmaxf(m2.y, 0.0f), 1.0f);
                const float d0 = expf(acc[mi][ni][rh * 2]) * mc0;
                const float d1 = expf(acc[mi][ni][rh * 2 + 1]) * mc1;
                part += d0 + d1;
                store_split2(d0, d1, dh + col, dl + col);
            }
            atomicAdd(&rsum[lr], part);
        }
    }
    __syncthreads();
    if (tid < 128) atomicAdd(&g_rowsum[(size_t)b * Sn + s0 + tid], rsum[tid]);
}

// O = (delta @ V) / (rowsum + 1e-10).  grid = (e=4, s=16, b=8)
__global__ __launch_bounds__(256) void outgemm_h(float* __restrict__ out) {
    const int b = blockIdx.z;
    const int s0 = blockIdx.y * 128;
    const int e0 = blockIdx.x * 128;
    const size_t doff = ((size_t)b * Sn + s0) * Sn;
    const size_t voff = ((size_t)b * En + e0) * Sn;
    float acc[4][4][4] = {};
    hmma_gemm(g_dhi + doff, g_dlo + doff, g_vThi + voff, g_vTlo + voff, Sn, Sn,
              Sn, acc);
    const int tid = threadIdx.x;
    const int w = tid >> 5, l = tid & 31;
    const int wm = (w & 1) * 64, wn = (w >> 1) * 32;
#pragma unroll
    for (int mi = 0; mi < 4; mi++) {
#pragma unroll
        for (int rh = 0; rh < 2; rh++) {
            const int lr = wm + mi * 16 + (l >> 2) + rh * 8;
            const size_t grow = (size_t)b * Sn + s0 + lr;
            const float inv = 1.0f / (g_rowsum[grow] + 1e-10f);
            float* orow = out + grow * En + e0;
#pragma unroll
            for (int ni = 0; ni < 4; ni++) {
                const int col = wn + ni * 8 + (l & 3) * 2;
                *(float2*)(orow + col) =
                    make_float2(acc[mi][ni][rh * 2] * inv,
                                acc[mi][ni][rh * 2 + 1] * inv);
            }
        }
    }
}

// ---------------------------------------------------------------------------
extern "C" void kernel_launch(void* const* d_in, const int* in_sizes, int n_in,
                              void* d_out, int out_size) {
    const int* key_seq = (const int*)d_in[0];
    const int* value_seq = (const int*)d_in[1];
    const float* hidden = (const float*)d_in[2];
    const float* mask = (const float*)d_in[3];
    const float* key_emb = (const float*)d_in[5];
    const float* value_emb = (const float*)d_in[6];
    const float* weight = (const float*)d_in[7];
    float* out = (float*)d_out;

    split_hidden<<<(size_t)BSn * En / 8 / 256, 256>>>(hidden);
    transpose_w<<<En * En / 256, 256>>>(weight);
    gather_k<<<BSn, 128>>>(key_seq, key_emb);
    gather_vT<<<dim3(Sn / 64, En / 64, Bn), 256>>>(value_seq, value_emb);
    zero_rowsum<<<BSn / 256, 256>>>();
    qgemm_h<<<dim3(En / 128, BSn / 128), 256>>>();
    scores_h<<<dim3(Sn / 128, Sn / 128, Bn), 256>>>(mask);
    outgemm_h<<<dim3(En / 128, Sn / 128, Bn), 256>>>(out);
}

// round 5
// speedup vs baseline: 3.1714x; 2.1653x over previous
#include <cuda_runtime.h>
#include <cuda_fp16.h>
#include <math.h>
#include <stdint.h>

#define Bn 8
#define Sn 2048
#define En 512
#define BSn (Bn * Sn)  // 16384

__device__ __constant__ float c_inv_scale = 0.044194173824159216f; // 1/sqrt(512)

// ---------------- scratch (static device arrays; no runtime alloc) --------
__device__ __half g_hhi[(size_t)BSn * En];
__device__ __half g_hlo[(size_t)BSn * En];
__device__ __half g_wThi[(size_t)En * En];   // [e_out][e_in]
__device__ __half g_wTlo[(size_t)En * En];
__device__ __half g_qhi[(size_t)BSn * En];   // pre-scaled by 1/sqrt(E)
__device__ __half g_qlo[(size_t)BSn * En];
__device__ __half g_khi[(size_t)BSn * En];
__device__ __half g_klo[(size_t)BSn * En];
__device__ __half g_vThi[(size_t)Bn * En * Sn];  // [b][e][t]
__device__ __half g_vTlo[(size_t)Bn * En * Sn];
__device__ __half g_dhi[(size_t)Bn * Sn * Sn];   // delta [b*S + s][t]
__device__ __half g_dlo[(size_t)Bn * Sn * Sn];
__device__ float g_rowsum[BSn];

// ---------------- helpers ---------------------------------------------
__device__ __forceinline__ uint32_t smem_u32(const void* p) {
    uint32_t a;
    asm("{ .reg .u64 t; cvta.to.shared.u64 t, %1; cvt.u32.u64 %0, t; }"
        : "=r"(a) : "l"(p));
    return a;
}
__device__ __forceinline__ void ldsm_x4(uint32_t (&r)[4], uint32_t addr) {
    asm volatile(
        "ldmatrix.sync.aligned.m8n8.x4.shared.b16 {%0,%1,%2,%3}, [%4];"
        : "=r"(r[0]), "=r"(r[1]), "=r"(r[2]), "=r"(r[3]) : "r"(addr));
}
__device__ __forceinline__ void mma16816(float (&d)[4], const uint32_t (&a)[4],
                                         uint32_t b0, uint32_t b1) {
    asm volatile(
        "mma.sync.aligned.m16n8k16.row.col.f32.f16.f16.f32 "
        "{%0,%1,%2,%3}, {%4,%5,%6,%7}, {%8,%9}, {%0,%1,%2,%3};"
        : "+f"(d[0]), "+f"(d[1]), "+f"(d[2]), "+f"(d[3])
        : "r"(a[0]), "r"(a[1]), "r"(a[2]), "r"(a[3]), "r"(b0), "r"(b1));
}
#define CPA16(dst, src) \
    asm volatile("cp.async.ca.shared.global [%0], [%1], 16;" \
                 :: "r"(dst), "l"(src) : "memory")
#define CPA_COMMIT() asm volatile("cp.async.commit_group;" ::: "memory")
#define CPA_WAIT1() asm volatile("cp.async.wait_group 1;" ::: "memory")
#define CPA_WAIT0() asm volatile("cp.async.wait_group 0;" ::: "memory")

__device__ __forceinline__ void split_f(float x, __half& h, __half& l) {
    h = __float2half_rn(x);
    l = __float2half_rn(x - __half2float(h));
}
__device__ __forceinline__ uint32_t h2u(__half a, __half b) {
    __half2 p = __halves2half2(a, b);
    return *reinterpret_cast<uint32_t*>(&p);
}
__device__ __forceinline__ void store_split2(float x, float y, __half* hi,
                                             __half* lo) {
    __half hx, lx, hy, ly;
    split_f(x, hx, lx);
    split_f(y, hy, ly);
    *(uint32_t*)hi = h2u(hx, hy);
    *(uint32_t*)lo = h2u(lx, ly);
}

// ---------------------------------------------------------------------------
// Fused 3-product HMMA mainloop:
//   acc += Ahi·Bhi^T + Alo·Bhi^T + Ahi·Blo^T   over K = ktot
// Each 32-wide K chunk loads all 4 tiles ONCE (cp.async, double-buffered) and
// issues all 3 MMA products. 256 threads, 128x128 block tile, warp 64x32.
// smem: 4 tiles x 2 buffers x [128][40] halves = 81920 B (dynamic).
// ---------------------------------------------------------------------------
#define PAD 40
#define TILEH (128 * PAD)          // halves per tile buffer
#define TILEB (TILEH * 2)          // bytes per tile buffer
#define SMEM_BYTES (8 * TILEB)     // 81920

__device__ __forceinline__ void hmma_gemm3(
    const __half* __restrict__ Ahi, const __half* __restrict__ Alo,
    const __half* __restrict__ Bhi, const __half* __restrict__ Blo,
    int lda, int ldb, int ktot, float (&acc)[4][4][4]) {
    extern __shared__ __align__(16) __half sm[];
    const uint32_t s0 = smem_u32(sm);
    // tile bases (bytes): As_hi 0 | As_lo 2*TILEB | Bs_hi 4*TILEB | Bs_lo 6*TILEB
    const int tid = threadIdx.x;
    const int w = tid >> 5, l = tid & 31;
    const int wm = (w & 1) * 64, wn = (w >> 1) * 32;
    const int lrow = l & 7, quad = l >> 3;

    // loader mapping: row = tid>>1, two 16B segs at half-col c, c+8
    const int grow = tid >> 1;
    const int gc = (tid & 1) * 16;
    const uint32_t dst_row = (uint32_t)(grow * PAD + gc) * 2;  // byte offset in tile

    const int nck = ktot / 32;

    // ldmatrix fragment addresses (hi tiles; lo = +2*TILEB / +2*TILEB)
    uint32_t a_addr[4][2], b_addr[2][2];
#pragma unroll
    for (int mi = 0; mi < 4; mi++)
#pragma unroll
        for (int ks = 0; ks < 2; ks++)
            a_addr[mi][ks] = s0 + ((wm + mi * 16 + (quad & 1) * 8 + lrow) * PAD +
                                   ks * 16 + (quad >> 1) * 8) * 2;
#pragma unroll
    for (int bi = 0; bi < 2; bi++)
#pragma unroll
        for (int ks = 0; ks < 2; ks++)
            b_addr[bi][ks] = s0 + 4 * TILEB +
                             ((wn + bi * 16 + (quad >> 1) * 8 + lrow) * PAD +
                              ks * 16 + (quad & 1) * 8) * 2;

    // chunk loader: 8 cp.async of 16B per thread
    auto load_chunk = [&](int kc, int buf) {
        const uint32_t d = dst_row + (buf ? TILEB : 0);
        const __half* pa = Ahi + (size_t)grow * lda + kc + gc;
        const __half* pl = Alo + (size_t)grow * lda + kc + gc;
        const __half* pb = Bhi + (size_t)grow * ldb + kc + gc;
        const __half* pq = Blo + (size_t)grow * ldb + kc + gc;
        CPA16(s0 + 0 * TILEB * 2 + d, pa);
        CPA16(s0 + 0 * TILEB * 2 + d + 16, pa + 8);
        CPA16(s0 + 1 * TILEB * 2 + d, pl);
        CPA16(s0 + 1 * TILEB * 2 + d + 16, pl + 8);
        CPA16(s0 + 2 * TILEB * 2 + d, pb);
        CPA16(s0 + 2 * TILEB * 2 + d + 16, pb + 8);
        CPA16(s0 + 3 * TILEB * 2 + d, pq);
        CPA16(s0 + 3 * TILEB * 2 + d + 16, pq + 8);
    };

    load_chunk(0, 0);
    CPA_COMMIT();

    for (int c = 0; c < nck; c++) {
        if (c + 1 < nck) {
            load_chunk((c + 1) * 32, (c + 1) & 1);
            CPA_COMMIT();
            CPA_WAIT1();
        } else {
            CPA_WAIT0();
        }
        __syncthreads();
        const uint32_t boff = (c & 1) ? (uint32_t)TILEB : 0u;
#pragma unroll
        for (int ks = 0; ks < 2; ks++) {
            uint32_t ah[4][4], bh[2][4];
#pragma unroll
            for (int mi = 0; mi < 4; mi++) ldsm_x4(ah[mi], a_addr[mi][ks] + boff);
#pragma unroll
            for (int bi = 0; bi < 2; bi++) ldsm_x4(bh[bi], b_addr[bi][ks] + boff);
            // P1: Ahi * Bhi
#pragma unroll
            for (int mi = 0; mi < 4; mi++)
#pragma unroll
                for (int ni = 0; ni < 4; ni++)
                    mma16816(acc[mi][ni], ah[mi], bh[ni >> 1][(ni & 1) * 2],
                             bh[ni >> 1][(ni & 1) * 2 + 1]);
            // P2: Alo * Bhi
            uint32_t al[4][4];
#pragma unroll
            for (int mi = 0; mi < 4; mi++)
                ldsm_x4(al[mi], a_addr[mi][ks] + boff + 2 * TILEB);
#pragma unroll
            for (int mi = 0; mi < 4; mi++)
#pragma unroll
                for (int ni = 0; ni < 4; ni++)
                    mma16816(acc[mi][ni], al[mi], bh[ni >> 1][(ni & 1) * 2],
                             bh[ni >> 1][(ni & 1) * 2 + 1]);
            // P3: Ahi * Blo
            uint32_t bl[2][4];
#pragma unroll
            for (int bi = 0; bi < 2; bi++)
                ldsm_x4(bl[bi], b_addr[bi][ks] + boff + 2 * TILEB);
#pragma unroll
            for (int mi = 0; mi < 4; mi++)
#pragma unroll
                for (int ni = 0; ni < 4; ni++)
                    mma16816(acc[mi][ni], ah[mi], bl[ni >> 1][(ni & 1) * 2],
                             bl[ni >> 1][(ni & 1) * 2 + 1]);
        }
        __syncthreads();
    }
}

// ---------------------------------------------------------------------------
// Prep kernels
// ---------------------------------------------------------------------------
__global__ __launch_bounds__(256) void split_hidden(const float* __restrict__ h) {
    const size_t i8 = ((size_t)blockIdx.x * 256 + threadIdx.x) * 8;
    const float4 f0 = *(const float4*)(h + i8);
    const float4 f1 = *(const float4*)(h + i8 + 4);
    const float v[8] = {f0.x, f0.y, f0.z, f0.w, f1.x, f1.y, f1.z, f1.w};
    __half hh[8], ll[8];
#pragma unroll
    for (int j = 0; j < 8; j++) split_f(v[j], hh[j], ll[j]);
    *(uint4*)(g_hhi + i8) = make_uint4(h2u(hh[0], hh[1]), h2u(hh[2], hh[3]),
                                       h2u(hh[4], hh[5]), h2u(hh[6], hh[7]));
    *(uint4*)(g_hlo + i8) = make_uint4(h2u(ll[0], ll[1]), h2u(ll[2], ll[3]),
                                       h2u(ll[4], ll[5]), h2u(ll[6], ll[7]));
}

__global__ __launch_bounds__(256) void transpose_w(const float* __restrict__ W) {
    const int idx = blockIdx.x * 256 + threadIdx.x;  // over 512*512
    const int eo = idx >> 9;
    const int ei = idx & 511;
    const float x = W[(size_t)ei * En + eo];
    __half hh, ll;
    split_f(x, hh, ll);
    g_wThi[idx] = hh;
    g_wTlo[idx] = ll;
}

__global__ __launch_bounds__(128) void gather_k(const int* __restrict__ kseq,
                                                const float* __restrict__ kemb) {
    const int row = blockIdx.x;
    const int t = threadIdx.x;  // 0..127
    const int ki = kseq[row];
    const float4 f = *(const float4*)(kemb + (size_t)ki * En + t * 4);
    __half h0, l0, h1, l1, h2, l2, h3, l3;
    split_f(f.x, h0, l0);
    split_f(f.y, h1, l1);
    split_f(f.z, h2, l2);
    split_f(f.w, h3, l3);
    *(uint2*)(g_khi + (size_t)row * En + t * 4) = make_uint2(h2u(h0, h1), h2u(h2, h3));
    *(uint2*)(g_klo + (size_t)row * En + t * 4) = make_uint2(h2u(l0, l1), h2u(l2, l3));
}

__global__ __launch_bounds__(256) void gather_vT(const int* __restrict__ vseq,
                                                 const float* __restrict__ vemb) {
    __shared__ float tile[64][65];
    const int b = blockIdx.z;
    const int e0 = blockIdx.y * 64;
    const int t0 = blockIdx.x * 64;
    const int tid = threadIdx.x;
    const int tr = tid >> 4;
    const int tc = (tid & 15) * 4;
#pragma unroll
    for (int rr = 0; rr < 4; rr++) {
        const int tl = tr + rr * 16;
        const int vi = vseq[b * Sn + t0 + tl];
        const float4 f = *(const float4*)(vemb + (size_t)vi * En + e0 + tc);
        tile[tl][tc + 0] = f.x;
        tile[tl][tc + 1] = f.y;
        tile[tl][tc + 2] = f.z;
        tile[tl][tc + 3] = f.w;
    }
    __syncthreads();
    const int er = tid >> 3;
    const int seg = (tid & 7) * 8;
#pragma unroll
    for (int pp = 0; pp < 2; pp++) {
        const int el = er + pp * 32;
        __half hh[8], ll[8];
#pragma unroll
        for (int j = 0; j < 8; j++) split_f(tile[seg + j][el], hh[j], ll[j]);
        const size_t o = ((size_t)b * En + e0 + el) * Sn + t0 + seg;
        *(uint4*)(g_vThi + o) = make_uint4(h2u(hh[0], hh[1]), h2u(hh[2], hh[3]),
                                           h2u(hh[4], hh[5]), h2u(hh[6], hh[7]));
        *(uint4*)(g_vTlo + o) = make_uint4(h2u(ll[0], ll[1]), h2u(ll[2], ll[3]),
                                           h2u(ll[4], ll[5]), h2u(ll[6], ll[7]));
    }
}

__global__ __launch_bounds__(256) void zero_rowsum() {
    g_rowsum[blockIdx.x * 256 + threadIdx.x] = 0.0f;
}

// ---------------------------------------------------------------------------
// GEMM kernels (256 threads, dynamic smem SMEM_BYTES)
// ---------------------------------------------------------------------------
__global__ __launch_bounds__(256) void qgemm_h() {
    const int s0 = blockIdx.y * 128;
    const int n0 = blockIdx.x * 128;
    float acc[4][4][4] = {};
    hmma_gemm3(g_hhi + (size_t)s0 * En, g_hlo + (size_t)s0 * En,
               g_wThi + (size_t)n0 * En, g_wTlo + (size_t)n0 * En, En, En, En,
               acc);
    const int tid = threadIdx.x;
    const int w = tid >> 5, l = tid & 31;
    const int wm = (w & 1) * 64, wn = (w >> 1) * 32;
#pragma unroll
    for (int mi = 0; mi < 4; mi++) {
#pragma unroll
        for (int rh = 0; rh < 2; rh++) {
            const int row = s0 + wm + mi * 16 + (l >> 2) + rh * 8;
#pragma unroll
            for (int ni = 0; ni < 4; ni++) {
                const int col = n0 + wn + ni * 8 + (l & 3) * 2;
                const size_t o = (size_t)row * En + col;
                store_split2(acc[mi][ni][rh * 2] * c_inv_scale,
                             acc[mi][ni][rh * 2 + 1] * c_inv_scale,
                             g_qhi + o, g_qlo + o);
            }
        }
    }
}

__global__ __launch_bounds__(256) void scores_h(const float* __restrict__ mask) {
    const int b = blockIdx.z;
    const int s0 = blockIdx.y * 128;
    const int t0 = blockIdx.x * 128;
    const size_t qoff = ((size_t)b * Sn + s0) * En;
    const size_t koff = ((size_t)b * Sn + t0) * En;
    float acc[4][4][4] = {};
    hmma_gemm3(g_qhi + qoff, g_qlo + qoff, g_khi + koff, g_klo + koff, En, En,
               En, acc);
    __shared__ float rsum[128];
    const int tid = threadIdx.x;
    if (tid < 128) rsum[tid] = 0.0f;
    __syncthreads();
    const int w = tid >> 5, l = tid & 31;
    const int wm = (w & 1) * 64, wn = (w >> 1) * 32;
#pragma unroll
    for (int mi = 0; mi < 4; mi++) {
#pragma unroll
        for (int rh = 0; rh < 2; rh++) {
            const int lr = wm + mi * 16 + (l >> 2) + rh * 8;
            const size_t grow = (size_t)b * Sn + s0 + lr;
            const float* mrow = mask + grow * Sn + t0;
            __half* dh = g_dhi + grow * Sn + t0;
            __half* dl = g_dlo + grow * Sn + t0;
            float part = 0.0f;
#pragma unroll
            for (int ni = 0; ni < 4; ni++) {
                const int col = wn + ni * 8 + (l & 3) * 2;
                const float2 m2 = *(const float2*)(mrow + col);
                const float mc0 = fminf(fmaxf(m2.x, 0.0f), 1.0f);
                const float mc1 = fminf(fmaxf(m2.y, 0.0f), 1.0f);
                const float d0 = __expf(acc[mi][ni][rh * 2]) * mc0;
                const float d1 = __expf(acc[mi][ni][rh * 2 + 1]) * mc1;
                part += d0 + d1;
                store_split2(d0, d1, dh + col, dl + col);
            }
            atomicAdd(&rsum[lr], part);
        }
    }
    __syncthreads();
    if (tid < 128) atomicAdd(&g_rowsum[(size_t)b * Sn + s0 + tid], rsum[tid]);
}

__global__ __launch_bounds__(256) void outgemm_h(float* __restrict__ out) {
    const int b = blockIdx.z;
    const int s0 = blockIdx.y * 128;
    const int e0 = blockIdx.x * 128;
    const size_t doff = ((size_t)b * Sn + s0) * Sn;
    const size_t voff = ((size_t)b * En + e0) * Sn;
    float acc[4][4][4] = {};
    hmma_gemm3(g_dhi + doff, g_dlo + doff, g_vThi + voff, g_vTlo + voff, Sn, Sn,
               Sn, acc);
    const int tid = threadIdx.x;
    const int w = tid >> 5, l = tid & 31;
    const int wm = (w & 1) * 64, wn = (w >> 1) * 32;
#pragma unroll
    for (int mi = 0; mi < 4; mi++) {
#pragma unroll
        for (int rh = 0; rh < 2; rh++) {
            const int lr = wm + mi * 16 + (l >> 2) + rh * 8;
            const size_t grow = (size_t)b * Sn + s0 + lr;
            const float inv = 1.0f / (g_rowsum[grow] + 1e-10f);
            float* orow = out + grow * En + e0;
#pragma unroll
            for (int ni = 0; ni < 4; ni++) {
                const int col = wn + ni * 8 + (l & 3) * 2;
                *(float2*)(orow + col) =
                    make_float2(acc[mi][ni][rh * 2] * inv,
                                acc[mi][ni][rh * 2 + 1] * inv);
            }
        }
    }
}

// ---------------------------------------------------------------------------
extern "C" void kernel_launch(void* const* d_in, const int* in_sizes, int n_in,
                              void* d_out, int out_size) {
    const int* key_seq = (const int*)d_in[0];
    const int* value_seq = (const int*)d_in[1];
    const float* hidden = (const float*)d_in[2];
    const float* mask = (const float*)d_in[3];
    const float* key_emb = (const float*)d_in[5];
    const float* value_emb = (const float*)d_in[6];
    const float* weight = (const float*)d_in[7];
    float* out = (float*)d_out;

    cudaFuncSetAttribute(qgemm_h, cudaFuncAttributeMaxDynamicSharedMemorySize,
                         SMEM_BYTES);
    cudaFuncSetAttribute(scores_h, cudaFuncAttributeMaxDynamicSharedMemorySize,
                         SMEM_BYTES);
    cudaFuncSetAttribute(outgemm_h, cudaFuncAttributeMaxDynamicSharedMemorySize,
                         SMEM_BYTES);

    split_hidden<<<(size_t)BSn * En / 8 / 256, 256>>>(hidden);
    transpose_w<<<En * En / 256, 256>>>(weight);
    gather_k<<<BSn, 128>>>(key_seq, key_emb);
    gather_vT<<<dim3(Sn / 64, En / 64, Bn), 256>>>(value_seq, value_emb);
    zero_rowsum<<<BSn / 256, 256>>>();
    qgemm_h<<<dim3(En / 128, BSn / 128), 256, SMEM_BYTES>>>();
    scores_h<<<dim3(Sn / 128, Sn / 128, Bn), 256, SMEM_BYTES>>>(mask);
    outgemm_h<<<dim3(En / 128, Sn / 128, Bn), 256, SMEM_BYTES>>>(out);
}

// round 6
// speedup vs baseline: 5.0246x; 1.5844x over previous
#include <cuda_runtime.h>
#include <cuda_fp16.h>
#include <math.h>
#include <stdint.h>

#define Bn 8
#define Sn 2048
#define En 512
#define BSn (Bn * Sn)  // 16384

__device__ __constant__ float c_inv_scale = 0.044194173824159216f; // 1/sqrt(512)

// ---------------- scratch ---------------------------------------------------
__device__ __half g_hhi[(size_t)BSn * En];
__device__ __half g_hlo[(size_t)BSn * En];
__device__ __half g_wThi[(size_t)En * En];       // [e_out][e_in]
__device__ __half g_qhi[(size_t)BSn * En];       // pre-scaled by 1/sqrt(E)
__device__ __half g_qlo[(size_t)BSn * En];
__device__ __half g_khi[(size_t)BSn * En];
__device__ __half g_vThi[(size_t)Bn * En * Sn];  // [b][e][t]
__device__ __half g_dhi[(size_t)Bn * Sn * Sn];   // delta fp16 [b*S+s][t]
__device__ float g_rowsum[BSn];

// ---------------- helpers ----------------------------------------------------
__device__ __forceinline__ uint32_t smem_u32(const void* p) {
    uint32_t a;
    asm("{ .reg .u64 t; cvta.to.shared.u64 t, %1; cvt.u32.u64 %0, t; }"
        : "=r"(a) : "l"(p));
    return a;
}
__device__ __forceinline__ void ldsm_x4(uint32_t (&r)[4], uint32_t addr) {
    asm volatile(
        "ldmatrix.sync.aligned.m8n8.x4.shared.b16 {%0,%1,%2,%3}, [%4];"
        : "=r"(r[0]), "=r"(r[1]), "=r"(r[2]), "=r"(r[3]) : "r"(addr));
}
__device__ __forceinline__ void mma16816(float (&d)[4], const uint32_t (&a)[4],
                                         uint32_t b0, uint32_t b1) {
    asm volatile(
        "mma.sync.aligned.m16n8k16.row.col.f32.f16.f16.f32 "
        "{%0,%1,%2,%3}, {%4,%5,%6,%7}, {%8,%9}, {%0,%1,%2,%3};"
        : "+f"(d[0]), "+f"(d[1]), "+f"(d[2]), "+f"(d[3])
        : "r"(a[0]), "r"(a[1]), "r"(a[2]), "r"(a[3]), "r"(b0), "r"(b1));
}
#define CPA16(dst, src) \
    asm volatile("cp.async.ca.shared.global [%0], [%1], 16;" \
                 :: "r"(dst), "l"(src) : "memory")
#define CPA_COMMIT() asm volatile("cp.async.commit_group;" ::: "memory")
#define CPA_WAIT1() asm volatile("cp.async.wait_group 1;" ::: "memory")
#define CPA_WAIT0() asm volatile("cp.async.wait_group 0;" ::: "memory")

__device__ __forceinline__ void split_f(float x, __half& h, __half& l) {
    h = __float2half_rn(x);
    l = __float2half_rn(x - __half2float(h));
}
__device__ __forceinline__ uint32_t h2u(__half a, __half b) {
    __half2 p = __halves2half2(a, b);
    return *reinterpret_cast<uint32_t*>(&p);
}

// ---------------------------------------------------------------------------
// 3-stage cp.async pipelined HMMA mainloop, templated on product count.
//   NPROD==2: acc += Ahi·Bhi^T + Alo·Bhi^T   (tiles: Ahi, Alo, Bhi)
//   NPROD==1: acc += Ahi·Bhi^T               (tiles: Ahi, Bhi)
// 256 threads, block tile 128x128, K-chunk 32, warp tile 64x32.
// Tile buffer: 128 rows x 40 halves (PAD) = 10240 B.
// ---------------------------------------------------------------------------
#define PAD 40
#define TILEB 10240
#define STAGES 3
#define SMEM_P2 (STAGES * 3 * TILEB)  // 92160
#define SMEM_P1 (STAGES * 2 * TILEB)  // 61440

template <int NPROD>
__device__ __forceinline__ void hmma_pipe(
    const __half* __restrict__ Ahi, const __half* __restrict__ Alo,
    const __half* __restrict__ Bhi, int lda, int ldb, int ktot,
    float (&acc)[4][4][4]) {
    extern __shared__ __align__(16) __half sm[];
    const uint32_t s0 = smem_u32(sm);
    constexpr uint32_t BOFFT = (NPROD == 2) ? 2 * TILEB : TILEB;  // B tile base
    constexpr uint32_t ST = (NPROD == 2) ? 3 * TILEB : 2 * TILEB; // stage stride

    const int tid = threadIdx.x;
    const int w = tid >> 5, l = tid & 31;
    const int wm = (w & 1) * 64, wn = (w >> 1) * 32;
    const int lrow = l & 7, quad = l >> 3;

    const int grow = tid >> 1;
    const int gc = (tid & 1) * 16;
    const uint32_t drow = (uint32_t)(grow * PAD + gc) * 2;

    const int nck = ktot / 32;

    uint32_t a_addr[4][2], b_addr[2][2];
#pragma unroll
    for (int mi = 0; mi < 4; mi++)
#pragma unroll
        for (int ks = 0; ks < 2; ks++)
            a_addr[mi][ks] = s0 + ((wm + mi * 16 + (quad & 1) * 8 + lrow) * PAD +
                                   ks * 16 + (quad >> 1) * 8) * 2;
#pragma unroll
    for (int bi = 0; bi < 2; bi++)
#pragma unroll
        for (int ks = 0; ks < 2; ks++)
            b_addr[bi][ks] = s0 + BOFFT +
                             ((wn + bi * 16 + (quad >> 1) * 8 + lrow) * PAD +
                              ks * 16 + (quad & 1) * 8) * 2;

    auto load_chunk = [&](int kc, int stg) {
        const uint32_t base = s0 + stg * ST + drow;
        const __half* pa = Ahi + (size_t)grow * lda + kc + gc;
        CPA16(base, pa);
        CPA16(base + 16, pa + 8);
        if (NPROD == 2) {
            const __half* pl = Alo + (size_t)grow * lda + kc + gc;
            CPA16(base + TILEB, pl);
            CPA16(base + TILEB + 16, pl + 8);
        }
        const __half* pb = Bhi + (size_t)grow * ldb + kc + gc;
        CPA16(base + BOFFT, pb);
        CPA16(base + BOFFT + 16, pb + 8);
    };

    load_chunk(0, 0);
    CPA_COMMIT();
    load_chunk(32, 1);
    CPA_COMMIT();

    int st = 0;
    uint32_t boff = 0;
    for (int c = 0; c < nck; c++) {
        if (c < nck - 1) {
            CPA_WAIT1();
        } else {
            CPA_WAIT0();
        }
        __syncthreads();
#pragma unroll
        for (int ks = 0; ks < 2; ks++) {
            uint32_t ah[4][4], bh[2][4];
#pragma unroll
            for (int mi = 0; mi < 4; mi++) ldsm_x4(ah[mi], a_addr[mi][ks] + boff);
#pragma unroll
            for (int bi = 0; bi < 2; bi++) ldsm_x4(bh[bi], b_addr[bi][ks] + boff);
#pragma unroll
            for (int mi = 0; mi < 4; mi++)
#pragma unroll
                for (int ni = 0; ni < 4; ni++)
                    mma16816(acc[mi][ni], ah[mi], bh[ni >> 1][(ni & 1) * 2],
                             bh[ni >> 1][(ni & 1) * 2 + 1]);
            if (NPROD == 2) {
                uint32_t al[4][4];
#pragma unroll
                for (int mi = 0; mi < 4; mi++)
                    ldsm_x4(al[mi], a_addr[mi][ks] + boff + TILEB);
#pragma unroll
                for (int mi = 0; mi < 4; mi++)
#pragma unroll
                    for (int ni = 0; ni < 4; ni++)
                        mma16816(acc[mi][ni], al[mi], bh[ni >> 1][(ni & 1) * 2],
                                 bh[ni >> 1][(ni & 1) * 2 + 1]);
            }
        }
        if (c + 2 < nck) {
            int ns = st + 2;
            if (ns >= STAGES) ns -= STAGES;
            load_chunk((c + 2) * 32, ns);
            CPA_COMMIT();
        }
        st++;
        boff += ST;
        if (st == STAGES) {
            st = 0;
            boff = 0;
        }
    }
}

// ---------------------------------------------------------------------------
// Prep kernels
// ---------------------------------------------------------------------------
__global__ __launch_bounds__(256) void split_hidden(const float* __restrict__ h) {
    const size_t i8 = ((size_t)blockIdx.x * 256 + threadIdx.x) * 8;
    const float4 f0 = *(const float4*)(h + i8);
    const float4 f1 = *(const float4*)(h + i8 + 4);
    const float v[8] = {f0.x, f0.y, f0.z, f0.w, f1.x, f1.y, f1.z, f1.w};
    __half hh[8], ll[8];
#pragma unroll
    for (int j = 0; j < 8; j++) split_f(v[j], hh[j], ll[j]);
    *(uint4*)(g_hhi + i8) = make_uint4(h2u(hh[0], hh[1]), h2u(hh[2], hh[3]),
                                       h2u(hh[4], hh[5]), h2u(hh[6], hh[7]));
    *(uint4*)(g_hlo + i8) = make_uint4(h2u(ll[0], ll[1]), h2u(ll[2], ll[3]),
                                       h2u(ll[4], ll[5]), h2u(ll[6], ll[7]));
}

__global__ __launch_bounds__(256) void transpose_w(const float* __restrict__ W) {
    const int idx = blockIdx.x * 256 + threadIdx.x;
    const int eo = idx >> 9;
    const int ei = idx & 511;
    g_wThi[idx] = __float2half_rn(W[(size_t)ei * En + eo]);
}

__global__ __launch_bounds__(128) void gather_k(const int* __restrict__ kseq,
                                                const float* __restrict__ kemb) {
    const int row = blockIdx.x;
    const int t = threadIdx.x;
    const int ki = kseq[row];
    const float4 f = *(const float4*)(kemb + (size_t)ki * En + t * 4);
    *(uint2*)(g_khi + (size_t)row * En + t * 4) =
        make_uint2(h2u(__float2half_rn(f.x), __float2half_rn(f.y)),
                   h2u(__float2half_rn(f.z), __float2half_rn(f.w)));
}

__global__ __launch_bounds__(256) void gather_vT(const int* __restrict__ vseq,
                                                 const float* __restrict__ vemb) {
    __shared__ float tile[64][65];
    const int b = blockIdx.z;
    const int e0 = blockIdx.y * 64;
    const int t0 = blockIdx.x * 64;
    const int tid = threadIdx.x;
    const int tr = tid >> 4;
    const int tc = (tid & 15) * 4;
#pragma unroll
    for (int rr = 0; rr < 4; rr++) {
        const int tl = tr + rr * 16;
        const int vi = vseq[b * Sn + t0 + tl];
        const float4 f = *(const float4*)(vemb + (size_t)vi * En + e0 + tc);
        tile[tl][tc + 0] = f.x;
        tile[tl][tc + 1] = f.y;
        tile[tl][tc + 2] = f.z;
        tile[tl][tc + 3] = f.w;
    }
    __syncthreads();
    const int er = tid >> 3;
    const int seg = (tid & 7) * 8;
#pragma unroll
    for (int pp = 0; pp < 2; pp++) {
        const int el = er + pp * 32;
        __half hh[8];
#pragma unroll
        for (int j = 0; j < 8; j++) hh[j] = __float2half_rn(tile[seg + j][el]);
        const size_t o = ((size_t)b * En + e0 + el) * Sn + t0 + seg;
        *(uint4*)(g_vThi + o) = make_uint4(h2u(hh[0], hh[1]), h2u(hh[2], hh[3]),
                                           h2u(hh[4], hh[5]), h2u(hh[6], hh[7]));
    }
}

__global__ __launch_bounds__(256) void zero_rowsum() {
    g_rowsum[blockIdx.x * 256 + threadIdx.x] = 0.0f;
}

// ---------------------------------------------------------------------------
// GEMM kernels
// ---------------------------------------------------------------------------
__global__ __launch_bounds__(256) void qgemm_h() {
    const int s0 = blockIdx.y * 128;
    const int n0 = blockIdx.x * 128;
    float acc[4][4][4] = {};
    hmma_pipe<2>(g_hhi + (size_t)s0 * En, g_hlo + (size_t)s0 * En,
                 g_wThi + (size_t)n0 * En, En, En, En, acc);
    const int tid = threadIdx.x;
    const int w = tid >> 5, l = tid & 31;
    const int wm = (w & 1) * 64, wn = (w >> 1) * 32;
#pragma unroll
    for (int mi = 0; mi < 4; mi++) {
#pragma unroll
        for (int rh = 0; rh < 2; rh++) {
            const int row = s0 + wm + mi * 16 + (l >> 2) + rh * 8;
#pragma unroll
            for (int ni = 0; ni < 4; ni++) {
                const int col = n0 + wn + ni * 8 + (l & 3) * 2;
                const size_t o = (size_t)row * En + col;
                const float x = acc[mi][ni][rh * 2] * c_inv_scale;
                const float y = acc[mi][ni][rh * 2 + 1] * c_inv_scale;
                __half hx, lx, hy, ly;
                split_f(x, hx, lx);
                split_f(y, hy, ly);
                *(uint32_t*)(g_qhi + o) = h2u(hx, hy);
                *(uint32_t*)(g_qlo + o) = h2u(lx, ly);
            }
        }
    }
}

__global__ __launch_bounds__(256) void scores_h(const float* __restrict__ mask) {
    const int b = blockIdx.z;
    const int s0 = blockIdx.y * 128;
    const int t0 = blockIdx.x * 128;
    const size_t qoff = ((size_t)b * Sn + s0) * En;
    const size_t koff = ((size_t)b * Sn + t0) * En;
    float acc[4][4][4] = {};
    hmma_pipe<2>(g_qhi + qoff, g_qlo + qoff, g_khi + koff, En, En, En, acc);
    __shared__ float rsum[128];
    const int tid = threadIdx.x;
    if (tid < 128) rsum[tid] = 0.0f;
    __syncthreads();
    const int w = tid >> 5, l = tid & 31;
    const int wm = (w & 1) * 64, wn = (w >> 1) * 32;
#pragma unroll
    for (int mi = 0; mi < 4; mi++) {
#pragma unroll
        for (int rh = 0; rh < 2; rh++) {
            const int lr = wm + mi * 16 + (l >> 2) + rh * 8;
            const size_t grow = (size_t)b * Sn + s0 + lr;
            const float* mrow = mask + grow * Sn + t0;
            __half* dh = g_dhi + grow * Sn + t0;
            float part = 0.0f;
#pragma unroll
            for (int ni = 0; ni < 4; ni++) {
                const int col = wn + ni * 8 + (l & 3) * 2;
                const float2 m2 = *(const float2*)(mrow + col);
                const float mc0 = fminf(fmaxf(m2.x, 0.0f), 1.0f);
                const float mc1 = fminf(fmaxf(m2.y, 0.0f), 1.0f);
                const __half h0 = __float2half_rn(__expf(acc[mi][ni][rh * 2]) * mc0);
                const __half h1 = __float2half_rn(__expf(acc[mi][ni][rh * 2 + 1]) * mc1);
                // rowsum from the QUANTIZED delta -> normalization self-consistent
                part += __half2float(h0) + __half2float(h1);
                *(uint32_t*)(dh + col) = h2u(h0, h1);
            }
            atomicAdd(&rsum[lr], part);
        }
    }
    __syncthreads();
    if (tid < 128) atomicAdd(&g_rowsum[(size_t)b * Sn + s0 + tid], rsum[tid]);
}

__global__ __launch_bounds__(256, 2) void outgemm_h(float* __restrict__ out) {
    const int b = blockIdx.z;
    const int s0 = blockIdx.y * 128;
    const int e0 = blockIdx.x * 128;
    const size_t doff = ((size_t)b * Sn + s0) * Sn;
    const size_t voff = ((size_t)b * En + e0) * Sn;
    float acc[4][4][4] = {};
    hmma_pipe<1>(g_dhi + doff, (const __half*)nullptr, g_vThi + voff, Sn, Sn,
                 Sn, acc);
    const int tid = threadIdx.x;
    const int w = tid >> 5, l = tid & 31;
    const int wm = (w & 1) * 64, wn = (w >> 1) * 32;
#pragma unroll
    for (int mi = 0; mi < 4; mi++) {
#pragma unroll
        for (int rh = 0; rh < 2; rh++) {
            const int lr = wm + mi * 16 + (l >> 2) + rh * 8;
            const size_t grow = (size_t)b * Sn + s0 + lr;
            const float inv = 1.0f / (g_rowsum[grow] + 1e-10f);
            float* orow = out + grow * En + e0;
#pragma unroll
            for (int ni = 0; ni < 4; ni++) {
                const int col = wn + ni * 8 + (l & 3) * 2;
                *(float2*)(orow + col) =
                    make_float2(acc[mi][ni][rh * 2] * inv,
                                acc[mi][ni][rh * 2 + 1] * inv);
            }
        }
    }
}

// ---------------------------------------------------------------------------
extern "C" void kernel_launch(void* const* d_in, const int* in_sizes, int n_in,
                              void* d_out, int out_size) {
    const int* key_seq = (const int*)d_in[0];
    const int* value_seq = (const int*)d_in[1];
    const float* hidden = (const float*)d_in[2];
    const float* mask = (const float*)d_in[3];
    const float* key_emb = (const float*)d_in[5];
    const float* value_emb = (const float*)d_in[6];
    const float* weight = (const float*)d_in[7];
    float* out = (float*)d_out;

    cudaFuncSetAttribute(qgemm_h, cudaFuncAttributeMaxDynamicSharedMemorySize,
                         SMEM_P2);
    cudaFuncSetAttribute(scores_h, cudaFuncAttributeMaxDynamicSharedMemorySize,
                         SMEM_P2);
    cudaFuncSetAttribute(outgemm_h, cudaFuncAttributeMaxDynamicSharedMemorySize,
                         SMEM_P1);

    split_hidden<<<(size_t)BSn * En / 8 / 256, 256>>>(hidden);
    transpose_w<<<En * En / 256, 256>>>(weight);
    gather_k<<<BSn, 128>>>(key_seq, key_emb);
    gather_vT<<<dim3(Sn / 64, En / 64, Bn), 256>>>(value_seq, value_emb);
    zero_rowsum<<<BSn / 256, 256>>>();
    qgemm_h<<<dim3(En / 128, BSn / 128), 256, SMEM_P2>>>();
    scores_h<<<dim3(Sn / 128, Sn / 128, Bn), 256, SMEM_P2>>>(mask);
    outgemm_h<<<dim3(En / 128, Sn / 128, Bn), 256, SMEM_P1>>>(out);
}

// round 7
// speedup vs baseline: 5.9654x; 1.1872x over previous
#include <cuda_runtime.h>
#include <cuda_fp16.h>
#include <math.h>
#include <stdint.h>

#define Bn 8
#define Sn 2048
#define En 512
#define BSn (Bn * Sn)  // 16384

__device__ __constant__ float c_inv_scale = 0.044194173824159216f; // 1/sqrt(512)

// ---------------- scratch ---------------------------------------------------
__device__ __half g_hhi[(size_t)BSn * En];
__device__ __half g_hlo[(size_t)BSn * En];
__device__ __half g_wThi[(size_t)En * En];       // [e_out][e_in]
__device__ __half g_qhi[(size_t)BSn * En];       // pre-scaled by 1/sqrt(E)
__device__ __half g_khi[(size_t)BSn * En];
__device__ __half g_vThi[(size_t)Bn * En * Sn];  // [b][e][t]
__device__ __half g_dhi[(size_t)Bn * Sn * Sn];   // delta fp16 [b*S+s][t]
__device__ float g_rowsum[BSn];

// ---------------- helpers ----------------------------------------------------
__device__ __forceinline__ uint32_t smem_u32(const void* p) {
    uint32_t a;
    asm("{ .reg .u64 t; cvta.to.shared.u64 t, %1; cvt.u32.u64 %0, t; }"
        : "=r"(a) : "l"(p));
    return a;
}
__device__ __forceinline__ void ldsm_x4(uint32_t (&r)[4], uint32_t addr) {
    asm volatile(
        "ldmatrix.sync.aligned.m8n8.x4.shared.b16 {%0,%1,%2,%3}, [%4];"
        : "=r"(r[0]), "=r"(r[1]), "=r"(r[2]), "=r"(r[3]) : "r"(addr));
}
__device__ __forceinline__ void mma16816(float (&d)[4], const uint32_t (&a)[4],
                                         uint32_t b0, uint32_t b1) {
    asm volatile(
        "mma.sync.aligned.m16n8k16.row.col.f32.f16.f16.f32 "
        "{%0,%1,%2,%3}, {%4,%5,%6,%7}, {%8,%9}, {%0,%1,%2,%3};"
        : "+f"(d[0]), "+f"(d[1]), "+f"(d[2]), "+f"(d[3])
        : "r"(a[0]), "r"(a[1]), "r"(a[2]), "r"(a[3]), "r"(b0), "r"(b1));
}
#define CPA16(dst, src) \
    asm volatile("cp.async.ca.shared.global [%0], [%1], 16;" \
                 :: "r"(dst), "l"(src) : "memory")
#define CPA_COMMIT() asm volatile("cp.async.commit_group;" ::: "memory")
#define CPA_WAIT1() asm volatile("cp.async.wait_group 1;" ::: "memory")
#define CPA_WAIT0() asm volatile("cp.async.wait_group 0;" ::: "memory")

__device__ __forceinline__ void split_f(float x, __half& h, __half& l) {
    h = __float2half_rn(x);
    l = __float2half_rn(x - __half2float(h));
}
__device__ __forceinline__ uint32_t h2u(__half a, __half b) {
    __half2 p = __halves2half2(a, b);
    return *reinterpret_cast<uint32_t*>(&p);
}

// ---------------------------------------------------------------------------
// 3-stage cp.async pipelined HMMA mainloop, templated on product count.
//   NPROD==2: acc += Ahi·Bhi^T + Alo·Bhi^T   (tiles: Ahi, Alo, Bhi)
//   NPROD==1: acc += Ahi·Bhi^T               (tiles: Ahi, Bhi)
// 256 threads, block tile 128x128, K-chunk 32, warp tile 64x32.
// Tile buffer: 128 rows x 40 halves (PAD) = 10240 B.
// ---------------------------------------------------------------------------
#define PAD 40
#define TILEB 10240
#define STAGES 3
#define SMEM_P2 (STAGES * 3 * TILEB)  // 92160
#define SMEM_P1 (STAGES * 2 * TILEB)  // 61440

template <int NPROD>
__device__ __forceinline__ void hmma_pipe(
    const __half* __restrict__ Ahi, const __half* __restrict__ Alo,
    const __half* __restrict__ Bhi, int lda, int ldb, int ktot,
    float (&acc)[4][4][4]) {
    extern __shared__ __align__(16) __half sm[];
    const uint32_t s0 = smem_u32(sm);
    constexpr uint32_t BOFFT = (NPROD == 2) ? 2 * TILEB : TILEB;  // B tile base
    constexpr uint32_t ST = (NPROD == 2) ? 3 * TILEB : 2 * TILEB; // stage stride

    const int tid = threadIdx.x;
    const int w = tid >> 5, l = tid & 31;
    const int wm = (w & 1) * 64, wn = (w >> 1) * 32;
    const int lrow = l & 7, quad = l >> 3;

    const int grow = tid >> 1;
    const int gc = (tid & 1) * 16;
    const uint32_t drow = (uint32_t)(grow * PAD + gc) * 2;

    const int nck = ktot / 32;

    uint32_t a_addr[4][2], b_addr[2][2];
#pragma unroll
    for (int mi = 0; mi < 4; mi++)
#pragma unroll
        for (int ks = 0; ks < 2; ks++)
            a_addr[mi][ks] = s0 + ((wm + mi * 16 + (quad & 1) * 8 + lrow) * PAD +
                                   ks * 16 + (quad >> 1) * 8) * 2;
#pragma unroll
    for (int bi = 0; bi < 2; bi++)
#pragma unroll
        for (int ks = 0; ks < 2; ks++)
            b_addr[bi][ks] = s0 + BOFFT +
                             ((wn + bi * 16 + (quad >> 1) * 8 + lrow) * PAD +
                              ks * 16 + (quad & 1) * 8) * 2;

    auto load_chunk = [&](int kc, int stg) {
        const uint32_t base = s0 + stg * ST + drow;
        const __half* pa = Ahi + (size_t)grow * lda + kc + gc;
        CPA16(base, pa);
        CPA16(base + 16, pa + 8);
        if (NPROD == 2) {
            const __half* pl = Alo + (size_t)grow * lda + kc + gc;
            CPA16(base + TILEB, pl);
            CPA16(base + TILEB + 16, pl + 8);
        }
        const __half* pb = Bhi + (size_t)grow * ldb + kc + gc;
        CPA16(base + BOFFT, pb);
        CPA16(base + BOFFT + 16, pb + 8);
    };

    load_chunk(0, 0);
    CPA_COMMIT();
    load_chunk(32, 1);
    CPA_COMMIT();

    int st = 0;
    uint32_t boff = 0;
    for (int c = 0; c < nck; c++) {
        if (c < nck - 1) {
            CPA_WAIT1();
        } else {
            CPA_WAIT0();
        }
        __syncthreads();
#pragma unroll
        for (int ks = 0; ks < 2; ks++) {
            uint32_t ah[4][4], bh[2][4];
#pragma unroll
            for (int mi = 0; mi < 4; mi++) ldsm_x4(ah[mi], a_addr[mi][ks] + boff);
#pragma unroll
            for (int bi = 0; bi < 2; bi++) ldsm_x4(bh[bi], b_addr[bi][ks] + boff);
#pragma unroll
            for (int mi = 0; mi < 4; mi++)
#pragma unroll
                for (int ni = 0; ni < 4; ni++)
                    mma16816(acc[mi][ni], ah[mi], bh[ni >> 1][(ni & 1) * 2],
                             bh[ni >> 1][(ni & 1) * 2 + 1]);
            if (NPROD == 2) {
                uint32_t al[4][4];
#pragma unroll
                for (int mi = 0; mi < 4; mi++)
                    ldsm_x4(al[mi], a_addr[mi][ks] + boff + TILEB);
#pragma unroll
                for (int mi = 0; mi < 4; mi++)
#pragma unroll
                    for (int ni = 0; ni < 4; ni++)
                        mma16816(acc[mi][ni], al[mi], bh[ni >> 1][(ni & 1) * 2],
                                 bh[ni >> 1][(ni & 1) * 2 + 1]);
            }
        }
        if (c + 2 < nck) {
            int ns = st + 2;
            if (ns >= STAGES) ns -= STAGES;
            load_chunk((c + 2) * 32, ns);
            CPA_COMMIT();
        }
        st++;
        boff += ST;
        if (st == STAGES) {
            st = 0;
            boff = 0;
        }
    }
}

// ---------------------------------------------------------------------------
// Prep kernels
// ---------------------------------------------------------------------------
__global__ __launch_bounds__(256) void split_hidden(const float* __restrict__ h) {
    const size_t i8 = ((size_t)blockIdx.x * 256 + threadIdx.x) * 8;
    const float4 f0 = *(const float4*)(h + i8);
    const float4 f1 = *(const float4*)(h + i8 + 4);
    const float v[8] = {f0.x, f0.y, f0.z, f0.w, f1.x, f1.y, f1.z, f1.w};
    __half hh[8], ll[8];
#pragma unroll
    for (int j = 0; j < 8; j++) split_f(v[j], hh[j], ll[j]);
    *(uint4*)(g_hhi + i8) = make_uint4(h2u(hh[0], hh[1]), h2u(hh[2], hh[3]),
                                       h2u(hh[4], hh[5]), h2u(hh[6], hh[7]));
    *(uint4*)(g_hlo + i8) = make_uint4(h2u(ll[0], ll[1]), h2u(ll[2], ll[3]),
                                       h2u(ll[4], ll[5]), h2u(ll[6], ll[7]));
}

__global__ __launch_bounds__(256) void transpose_w(const float* __restrict__ W) {
    const int idx = blockIdx.x * 256 + threadIdx.x;
    const int eo = idx >> 9;
    const int ei = idx & 511;
    g_wThi[idx] = __float2half_rn(W[(size_t)ei * En + eo]);
}

__global__ __launch_bounds__(128) void gather_k(const int* __restrict__ kseq,
                                                const float* __restrict__ kemb) {
    const int row = blockIdx.x;
    const int t = threadIdx.x;
    const int ki = kseq[row];
    const float4 f = *(const float4*)(kemb + (size_t)ki * En + t * 4);
    *(uint2*)(g_khi + (size_t)row * En + t * 4) =
        make_uint2(h2u(__float2half_rn(f.x), __float2half_rn(f.y)),
                   h2u(__float2half_rn(f.z), __float2half_rn(f.w)));
}

__global__ __launch_bounds__(256) void gather_vT(const int* __restrict__ vseq,
                                                 const float* __restrict__ vemb) {
    __shared__ float tile[64][65];
    const int b = blockIdx.z;
    const int e0 = blockIdx.y * 64;
    const int t0 = blockIdx.x * 64;
    const int tid = threadIdx.x;
    const int tr = tid >> 4;
    const int tc = (tid & 15) * 4;
#pragma unroll
    for (int rr = 0; rr < 4; rr++) {
        const int tl = tr + rr * 16;
        const int vi = vseq[b * Sn + t0 + tl];
        const float4 f = *(const float4*)(vemb + (size_t)vi * En + e0 + tc);
        tile[tl][tc + 0] = f.x;
        tile[tl][tc + 1] = f.y;
        tile[tl][tc + 2] = f.z;
        tile[tl][tc + 3] = f.w;
    }
    __syncthreads();
    const int er = tid >> 3;
    const int seg = (tid & 7) * 8;
#pragma unroll
    for (int pp = 0; pp < 2; pp++) {
        const int el = er + pp * 32;
        __half hh[8];
#pragma unroll
        for (int j = 0; j < 8; j++) hh[j] = __float2half_rn(tile[seg + j][el]);
        const size_t o = ((size_t)b * En + e0 + el) * Sn + t0 + seg;
        *(uint4*)(g_vThi + o) = make_uint4(h2u(hh[0], hh[1]), h2u(hh[2], hh[3]),
                                           h2u(hh[4], hh[5]), h2u(hh[6], hh[7]));
    }
}

__global__ __launch_bounds__(256) void zero_rowsum() {
    g_rowsum[blockIdx.x * 256 + threadIdx.x] = 0.0f;
}

// ---------------------------------------------------------------------------
// GEMM kernels
// ---------------------------------------------------------------------------
__global__ __launch_bounds__(256) void qgemm_h() {
    const int s0 = blockIdx.y * 128;
    const int n0 = blockIdx.x * 128;
    float acc[4][4][4] = {};
    hmma_pipe<2>(g_hhi + (size_t)s0 * En, g_hlo + (size_t)s0 * En,
                 g_wThi + (size_t)n0 * En, En, En, En, acc);
    const int tid = threadIdx.x;
    const int w = tid >> 5, l = tid & 31;
    const int wm = (w & 1) * 64, wn = (w >> 1) * 32;
#pragma unroll
    for (int mi = 0; mi < 4; mi++) {
#pragma unroll
        for (int rh = 0; rh < 2; rh++) {
            const int row = s0 + wm + mi * 16 + (l >> 2) + rh * 8;
#pragma unroll
            for (int ni = 0; ni < 4; ni++) {
                const int col = n0 + wn + ni * 8 + (l & 3) * 2;
                const size_t o = (size_t)row * En + col;
                *(uint32_t*)(g_qhi + o) =
                    h2u(__float2half_rn(acc[mi][ni][rh * 2] * c_inv_scale),
                        __float2half_rn(acc[mi][ni][rh * 2 + 1] * c_inv_scale));
            }
        }
    }
}

__global__ __launch_bounds__(256, 2) void scores_h(const float* __restrict__ mask) {
    const int b = blockIdx.z;
    const int s0 = blockIdx.y * 128;
    const int t0 = blockIdx.x * 128;
    const size_t qoff = ((size_t)b * Sn + s0) * En;
    const size_t koff = ((size_t)b * Sn + t0) * En;
    float acc[4][4][4] = {};
    hmma_pipe<1>(g_qhi + qoff, (const __half*)nullptr, g_khi + koff, En, En, En,
                 acc);
    __shared__ float rsum[128];
    const int tid = threadIdx.x;
    if (tid < 128) rsum[tid] = 0.0f;
    __syncthreads();
    const int w = tid >> 5, l = tid & 31;
    const int wm = (w & 1) * 64, wn = (w >> 1) * 32;
#pragma unroll
    for (int mi = 0; mi < 4; mi++) {
#pragma unroll
        for (int rh = 0; rh < 2; rh++) {
            const int lr = wm + mi * 16 + (l >> 2) + rh * 8;
            const size_t grow = (size_t)b * Sn + s0 + lr;
            const float* mrow = mask + grow * Sn + t0;
            __half* dh = g_dhi + grow * Sn + t0;
            float part = 0.0f;
#pragma unroll
            for (int ni = 0; ni < 4; ni++) {
                const int col = wn + ni * 8 + (l & 3) * 2;
                const float2 m2 = *(const float2*)(mrow + col);
                const float mc0 = fminf(fmaxf(m2.x, 0.0f), 1.0f);
                const float mc1 = fminf(fmaxf(m2.y, 0.0f), 1.0f);
                const __half h0 = __float2half_rn(__expf(acc[mi][ni][rh * 2]) * mc0);
                const __half h1 = __float2half_rn(__expf(acc[mi][ni][rh * 2 + 1]) * mc1);
                // rowsum from the QUANTIZED delta -> normalization self-consistent
                part += __half2float(h0) + __half2float(h1);
                *(uint32_t*)(dh + col) = h2u(h0, h1);
            }
            atomicAdd(&rsum[lr], part);
        }
    }
    __syncthreads();
    if (tid < 128) atomicAdd(&g_rowsum[(size_t)b * Sn + s0 + tid], rsum[tid]);
}

__global__ __launch_bounds__(256, 2) void outgemm_h(float* __restrict__ out) {
    const int b = blockIdx.z;
    const int s0 = blockIdx.y * 128;
    const int e0 = blockIdx.x * 128;
    const size_t doff = ((size_t)b * Sn + s0) * Sn;
    const size_t voff = ((size_t)b * En + e0) * Sn;
    float acc[4][4][4] = {};
    hmma_pipe<1>(g_dhi + doff, (const __half*)nullptr, g_vThi + voff, Sn, Sn,
                 Sn, acc);
    const int tid = threadIdx.x;
    const int w = tid >> 5, l = tid & 31;
    const int wm = (w & 1) * 64, wn = (w >> 1) * 32;
#pragma unroll
    for (int mi = 0; mi < 4; mi++) {
#pragma unroll
        for (int rh = 0; rh < 2; rh++) {
            const int lr = wm + mi * 16 + (l >> 2) + rh * 8;
            const size_t grow = (size_t)b * Sn + s0 + lr;
            const float inv = 1.0f / (g_rowsum[grow] + 1e-10f);
            float* orow = out + grow * En + e0;
#pragma unroll
            for (int ni = 0; ni < 4; ni++) {
                const int col = wn + ni * 8 + (l & 3) * 2;
                *(float2*)(orow + col) =
                    make_float2(acc[mi][ni][rh * 2] * inv,
                                acc[mi][ni][rh * 2 + 1] * inv);
            }
        }
    }
}

// ---------------------------------------------------------------------------
extern "C" void kernel_launch(void* const* d_in, const int* in_sizes, int n_in,
                              void* d_out, int out_size) {
    const int* key_seq = (const int*)d_in[0];
    const int* value_seq = (const int*)d_in[1];
    const float* hidden = (const float*)d_in[2];
    const float* mask = (const float*)d_in[3];
    const float* key_emb = (const float*)d_in[5];
    const float* value_emb = (const float*)d_in[6];
    const float* weight = (const float*)d_in[7];
    float* out = (float*)d_out;

    cudaFuncSetAttribute(qgemm_h, cudaFuncAttributeMaxDynamicSharedMemorySize,
                         SMEM_P2);
    cudaFuncSetAttribute(scores_h, cudaFuncAttributeMaxDynamicSharedMemorySize,
                         SMEM_P1);
    cudaFuncSetAttribute(outgemm_h, cudaFuncAttributeMaxDynamicSharedMemorySize,
                         SMEM_P1);

    split_hidden<<<(size_t)BSn * En / 8 / 256, 256>>>(hidden);
    transpose_w<<<En * En / 256, 256>>>(weight);
    gather_k<<<BSn, 128>>>(key_seq, key_emb);
    gather_vT<<<dim3(Sn / 64, En / 64, Bn), 256>>>(value_seq, value_emb);
    zero_rowsum<<<BSn / 256, 256>>>();
    qgemm_h<<<dim3(En / 128, BSn / 128), 256, SMEM_P2>>>();
    scores_h<<<dim3(Sn / 128, Sn / 128, Bn), 256, SMEM_P1>>>(mask);
    outgemm_h<<<dim3(En / 128, Sn / 128, Bn), 256, SMEM_P1>>>(out);
}

// round 8
// speedup vs baseline: 6.0263x; 1.0102x over previous
#include <cuda_runtime.h>
#include <cuda_fp16.h>
#include <math.h>
#include <stdint.h>

#define Bn 8
#define Sn 2048
#define En 512
#define BSn (Bn * Sn)  // 16384

__device__ __constant__ float c_inv_scale = 0.044194173824159216f; // 1/sqrt(512)

// ---------------- scratch ---------------------------------------------------
__device__ __half g_hhi[(size_t)BSn * En];
__device__ __half g_wThi[(size_t)En * En];       // [e_out][e_in]
__device__ __half g_qhi[(size_t)BSn * En];       // pre-scaled by 1/sqrt(E)
__device__ __half g_khi[(size_t)BSn * En];
__device__ __half g_vThi[(size_t)Bn * En * Sn];  // [b][e][t]
__device__ __half g_dhi[(size_t)Bn * Sn * Sn];   // delta fp16 [b*S+s][t]
__device__ float g_rowsum[BSn];

// ---------------- helpers ----------------------------------------------------
__device__ __forceinline__ uint32_t smem_u32(const void* p) {
    uint32_t a;
    asm("{ .reg .u64 t; cvta.to.shared.u64 t, %1; cvt.u32.u64 %0, t; }"
        : "=r"(a) : "l"(p));
    return a;
}
__device__ __forceinline__ void ldsm_x4(uint32_t (&r)[4], uint32_t addr) {
    asm volatile(
        "ldmatrix.sync.aligned.m8n8.x4.shared.b16 {%0,%1,%2,%3}, [%4];"
        : "=r"(r[0]), "=r"(r[1]), "=r"(r[2]), "=r"(r[3]) : "r"(addr));
}
__device__ __forceinline__ void mma16816(float (&d)[4], const uint32_t (&a)[4],
                                         uint32_t b0, uint32_t b1) {
    asm volatile(
        "mma.sync.aligned.m16n8k16.row.col.f32.f16.f16.f32 "
        "{%0,%1,%2,%3}, {%4,%5,%6,%7}, {%8,%9}, {%0,%1,%2,%3};"
        : "+f"(d[0]), "+f"(d[1]), "+f"(d[2]), "+f"(d[3])
        : "r"(a[0]), "r"(a[1]), "r"(a[2]), "r"(a[3]), "r"(b0), "r"(b1));
}
#define CPA16(dst, src) \
    asm volatile("cp.async.ca.shared.global [%0], [%1], 16;" \
                 :: "r"(dst), "l"(src) : "memory")
#define CPA_COMMIT() asm volatile("cp.async.commit_group;" ::: "memory")
#define CPA_WAIT2() asm volatile("cp.async.wait_group 2;" ::: "memory")
#define CPA_WAIT1() asm volatile("cp.async.wait_group 1;" ::: "memory")
#define CPA_WAIT0() asm volatile("cp.async.wait_group 0;" ::: "memory")

__device__ __forceinline__ uint32_t h2u(__half a, __half b) {
    __half2 p = __halves2half2(a, b);
    return *reinterpret_cast<uint32_t*>(&p);
}

// ---------------------------------------------------------------------------
// 4-stage cp.async pipelined fp16 HMMA mainloop (single product):
//   acc += A·B^T over K = ktot.  A,B K-major fp16, strides lda/ldb.
// 256 threads, block tile 128x128, K-chunk 32, warp tile 64x32.
// Tile buffer: 128 rows x 40 halves = 10240 B; stage = A tile + B tile.
// ---------------------------------------------------------------------------
#define PAD 40
#define TILEB 10240
#define STAGES 4
#define ST (2 * TILEB)
#define SMEM_GB (STAGES * ST)  // 81920

__device__ __forceinline__ void hmma_pipe(
    const __half* __restrict__ A, const __half* __restrict__ B, int lda,
    int ldb, int ktot, float (&acc)[4][4][4]) {
    extern __shared__ __align__(16) __half sm[];
    const uint32_t s0 = smem_u32(sm);

    const int tid = threadIdx.x;
    const int w = tid >> 5, l = tid & 31;
    const int wm = (w & 1) * 64, wn = (w >> 1) * 32;
    const int lrow = l & 7, quad = l >> 3;

    const int grow = tid >> 1;
    const int gc = (tid & 1) * 16;
    const uint32_t drow = (uint32_t)(grow * PAD + gc) * 2;

    const int nck = ktot / 32;

    uint32_t a_addr[4][2], b_addr[2][2];
#pragma unroll
    for (int mi = 0; mi < 4; mi++)
#pragma unroll
        for (int ks = 0; ks < 2; ks++)
            a_addr[mi][ks] = s0 + ((wm + mi * 16 + (quad & 1) * 8 + lrow) * PAD +
                                   ks * 16 + (quad >> 1) * 8) * 2;
#pragma unroll
    for (int bi = 0; bi < 2; bi++)
#pragma unroll
        for (int ks = 0; ks < 2; ks++)
            b_addr[bi][ks] = s0 + TILEB +
                             ((wn + bi * 16 + (quad >> 1) * 8 + lrow) * PAD +
                              ks * 16 + (quad & 1) * 8) * 2;

    auto load_chunk = [&](int c) {
        const uint32_t base = s0 + (uint32_t)(c & (STAGES - 1)) * ST + drow;
        const __half* pa = A + (size_t)grow * lda + c * 32 + gc;
        CPA16(base, pa);
        CPA16(base + 16, pa + 8);
        const __half* pb = B + (size_t)grow * ldb + c * 32 + gc;
        CPA16(base + TILEB, pb);
        CPA16(base + TILEB + 16, pb + 8);
    };

    load_chunk(0);
    CPA_COMMIT();
    load_chunk(1);
    CPA_COMMIT();
    load_chunk(2);
    CPA_COMMIT();

    for (int c = 0; c < nck; c++) {
        if (c <= nck - 3) {
            CPA_WAIT2();
        } else if (c == nck - 2) {
            CPA_WAIT1();
        } else {
            CPA_WAIT0();
        }
        __syncthreads();
        if (c + 3 < nck) {
            load_chunk(c + 3);
            CPA_COMMIT();
        }
        const uint32_t boff = (uint32_t)(c & (STAGES - 1)) * ST;
#pragma unroll
        for (int ks = 0; ks < 2; ks++) {
            uint32_t ah[4][4], bh[2][4];
#pragma unroll
            for (int mi = 0; mi < 4; mi++) ldsm_x4(ah[mi], a_addr[mi][ks] + boff);
#pragma unroll
            for (int bi = 0; bi < 2; bi++) ldsm_x4(bh[bi], b_addr[bi][ks] + boff);
#pragma unroll
            for (int mi = 0; mi < 4; mi++)
#pragma unroll
                for (int ni = 0; ni < 4; ni++)
                    mma16816(acc[mi][ni], ah[mi], bh[ni >> 1][(ni & 1) * 2],
                             bh[ni >> 1][(ni & 1) * 2 + 1]);
        }
    }
}

// ---------------------------------------------------------------------------
// Prep kernels
// ---------------------------------------------------------------------------
__global__ __launch_bounds__(256) void convert_hidden(const float* __restrict__ h) {
    const size_t i8 = ((size_t)blockIdx.x * 256 + threadIdx.x) * 8;
    const float4 f0 = *(const float4*)(h + i8);
    const float4 f1 = *(const float4*)(h + i8 + 4);
    *(uint4*)(g_hhi + i8) = make_uint4(
        h2u(__float2half_rn(f0.x), __float2half_rn(f0.y)),
        h2u(__float2half_rn(f0.z), __float2half_rn(f0.w)),
        h2u(__float2half_rn(f1.x), __float2half_rn(f1.y)),
        h2u(__float2half_rn(f1.z), __float2half_rn(f1.w)));
}

__global__ __launch_bounds__(256) void transpose_w(const float* __restrict__ W) {
    const int idx = blockIdx.x * 256 + threadIdx.x;
    const int eo = idx >> 9;
    const int ei = idx & 511;
    g_wThi[idx] = __float2half_rn(W[(size_t)ei * En + eo]);
}

__global__ __launch_bounds__(128) void gather_k(const int* __restrict__ kseq,
                                                const float* __restrict__ kemb) {
    const int row = blockIdx.x;
    const int t = threadIdx.x;
    const int ki = kseq[row];
    const float4 f = *(const float4*)(kemb + (size_t)ki * En + t * 4);
    *(uint2*)(g_khi + (size_t)row * En + t * 4) =
        make_uint2(h2u(__float2half_rn(f.x), __float2half_rn(f.y)),
                   h2u(__float2half_rn(f.z), __float2half_rn(f.w)));
}

__global__ __launch_bounds__(256) void gather_vT(const int* __restrict__ vseq,
                                                 const float* __restrict__ vemb) {
    __shared__ float tile[64][65];
    const int b = blockIdx.z;
    const int e0 = blockIdx.y * 64;
    const int t0 = blockIdx.x * 64;
    const int tid = threadIdx.x;
    const int tr = tid >> 4;
    const int tc = (tid & 15) * 4;
#pragma unroll
    for (int rr = 0; rr < 4; rr++) {
        const int tl = tr + rr * 16;
        const int vi = vseq[b * Sn + t0 + tl];
        const float4 f = *(const float4*)(vemb + (size_t)vi * En + e0 + tc);
        tile[tl][tc + 0] = f.x;
        tile[tl][tc + 1] = f.y;
        tile[tl][tc + 2] = f.z;
        tile[tl][tc + 3] = f.w;
    }
    __syncthreads();
    const int er = tid >> 3;
    const int seg = (tid & 7) * 8;
#pragma unroll
    for (int pp = 0; pp < 2; pp++) {
        const int el = er + pp * 32;
        __half hh[8];
#pragma unroll
        for (int j = 0; j < 8; j++) hh[j] = __float2half_rn(tile[seg + j][el]);
        const size_t o = ((size_t)b * En + e0 + el) * Sn + t0 + seg;
        *(uint4*)(g_vThi + o) = make_uint4(h2u(hh[0], hh[1]), h2u(hh[2], hh[3]),
                                           h2u(hh[4], hh[5]), h2u(hh[6], hh[7]));
    }
}

__global__ __launch_bounds__(256) void zero_rowsum() {
    g_rowsum[blockIdx.x * 256 + threadIdx.x] = 0.0f;
}

// ---------------------------------------------------------------------------
// GEMM kernels (256 threads, 2 CTAs/SM, dynamic smem SMEM_GB)
// ---------------------------------------------------------------------------
__global__ __launch_bounds__(256, 2) void qgemm_h() {
    const int s0 = blockIdx.y * 128;
    const int n0 = blockIdx.x * 128;
    float acc[4][4][4] = {};
    hmma_pipe(g_hhi + (size_t)s0 * En, g_wThi + (size_t)n0 * En, En, En, En,
              acc);
    const int tid = threadIdx.x;
    const int w = tid >> 5, l = tid & 31;
    const int wm = (w & 1) * 64, wn = (w >> 1) * 32;
#pragma unroll
    for (int mi = 0; mi < 4; mi++) {
#pragma unroll
        for (int rh = 0; rh < 2; rh++) {
            const int row = s0 + wm + mi * 16 + (l >> 2) + rh * 8;
#pragma unroll
            for (int ni = 0; ni < 4; ni++) {
                const int col = n0 + wn + ni * 8 + (l & 3) * 2;
                const size_t o = (size_t)row * En + col;
                *(uint32_t*)(g_qhi + o) =
                    h2u(__float2half_rn(acc[mi][ni][rh * 2] * c_inv_scale),
                        __float2half_rn(acc[mi][ni][rh * 2 + 1] * c_inv_scale));
            }
        }
    }
}

__global__ __launch_bounds__(256, 2) void scores_h(const float* __restrict__ mask) {
    const int b = blockIdx.z;
    const int s0 = blockIdx.y * 128;
    const int t0 = blockIdx.x * 128;
    const size_t qoff = ((size_t)b * Sn + s0) * En;
    const size_t koff = ((size_t)b * Sn + t0) * En;
    float acc[4][4][4] = {};
    hmma_pipe(g_qhi + qoff, g_khi + koff, En, En, En, acc);
    __shared__ float rsum[128];
    const int tid = threadIdx.x;
    if (tid < 128) rsum[tid] = 0.0f;
    __syncthreads();
    const int w = tid >> 5, l = tid & 31;
    const int wm = (w & 1) * 64, wn = (w >> 1) * 32;
#pragma unroll
    for (int mi = 0; mi < 4; mi++) {
#pragma unroll
        for (int rh = 0; rh < 2; rh++) {
            const int lr = wm + mi * 16 + (l >> 2) + rh * 8;
            const size_t grow = (size_t)b * Sn + s0 + lr;
            const float* mrow = mask + grow * Sn + t0;
            __half* dh = g_dhi + grow * Sn + t0;
            float part = 0.0f;
#pragma unroll
            for (int ni = 0; ni < 4; ni++) {
                const int col = wn + ni * 8 + (l & 3) * 2;
                const float2 m2 = *(const float2*)(mrow + col);
                const float mc0 = fminf(fmaxf(m2.x, 0.0f), 1.0f);
                const float mc1 = fminf(fmaxf(m2.y, 0.0f), 1.0f);
                const __half h0 = __float2half_rn(__expf(acc[mi][ni][rh * 2]) * mc0);
                const __half h1 = __float2half_rn(__expf(acc[mi][ni][rh * 2 + 1]) * mc1);
                // rowsum from the QUANTIZED delta -> normalization self-consistent
                part += __half2float(h0) + __half2float(h1);
                *(uint32_t*)(dh + col) = h2u(h0, h1);
            }
            atomicAdd(&rsum[lr], part);
        }
    }
    __syncthreads();
    if (tid < 128) atomicAdd(&g_rowsum[(size_t)b * Sn + s0 + tid], rsum[tid]);
}

__global__ __launch_bounds__(256, 2) void outgemm_h(float* __restrict__ out) {
    const int b = blockIdx.z;
    const int s0 = blockIdx.y * 128;
    const int e0 = blockIdx.x * 128;
    const size_t doff = ((size_t)b * Sn + s0) * Sn;
    const size_t voff = ((size_t)b * En + e0) * Sn;
    float acc[4][4][4] = {};
    hmma_pipe(g_dhi + doff, g_vThi + voff, Sn, Sn, Sn, acc);
    const int tid = threadIdx.x;
    const int w = tid >> 5, l = tid & 31;
    const int wm = (w & 1) * 64, wn = (w >> 1) * 32;
#pragma unroll
    for (int mi = 0; mi < 4; mi++) {
#pragma unroll
        for (int rh = 0; rh < 2; rh++) {
            const int lr = wm + mi * 16 + (l >> 2) + rh * 8;
            const size_t grow = (size_t)b * Sn + s0 + lr;
            const float inv = 1.0f / (g_rowsum[grow] + 1e-10f);
            float* orow = out + grow * En + e0;
#pragma unroll
            for (int ni = 0; ni < 4; ni++) {
                const int col = wn + ni * 8 + (l & 3) * 2;
                *(float2*)(orow + col) =
                    make_float2(acc[mi][ni][rh * 2] * inv,
                                acc[mi][ni][rh * 2 + 1] * inv);
            }
        }
    }
}

// ---------------------------------------------------------------------------
extern "C" void kernel_launch(void* const* d_in, const int* in_sizes, int n_in,
                              void* d_out, int out_size) {
    const int* key_seq = (const int*)d_in[0];
    const int* value_seq = (const int*)d_in[1];
    const float* hidden = (const float*)d_in[2];
    const float* mask = (const float*)d_in[3];
    const float* key_emb = (const float*)d_in[5];
    const float* value_emb = (const float*)d_in[6];
    const float* weight = (const float*)d_in[7];
    float* out = (float*)d_out;

    cudaFuncSetAttribute(qgemm_h, cudaFuncAttributeMaxDynamicSharedMemorySize,
                         SMEM_GB);
    cudaFuncSetAttribute(scores_h, cudaFuncAttributeMaxDynamicSharedMemorySize,
                         SMEM_GB);
    cudaFuncSetAttribute(outgemm_h, cudaFuncAttributeMaxDynamicSharedMemorySize,
                         SMEM_GB);

    convert_hidden<<<(size_t)BSn * En / 8 / 256, 256>>>(hidden);
    transpose_w<<<En * En / 256, 256>>>(weight);
    gather_k<<<BSn, 128>>>(key_seq, key_emb);
    gather_vT<<<dim3(Sn / 64, En / 64, Bn), 256>>>(value_seq, value_emb);
    zero_rowsum<<<BSn / 256, 256>>>();
    qgemm_h<<<dim3(En / 128, BSn / 128), 256, SMEM_GB>>>();
    scores_h<<<dim3(Sn / 128, Sn / 128, Bn), 256, SMEM_GB>>>(mask);
    outgemm_h<<<dim3(En / 128, Sn / 128, Bn), 256, SMEM_GB>>>(out);
}